// round 2
// baseline (speedup 1.0000x reference)
#include <cuda_runtime.h>
#include <cuda_bf16.h>
#include <math.h>

// Problem constants (fixed by the reference)
#define DIMN   2048
#define BATCH  4
#define LQ     4096
#define KC     576
#define KT     (KC + LQ)      // 4672 total keys per batch

// ---------------------------------------------------------------------------
// Scratch (static __device__ arrays — no allocation allowed)
// ---------------------------------------------------------------------------
__device__ float g_q    [(size_t)BATCH * LQ * DIMN];   // 134 MB
__device__ float g_kfull[(size_t)BATCH * KT * DIMN];   // 153 MB (cached + new)
__device__ float g_vfull[(size_t)BATCH * KT * DIMN];   // 153 MB
__device__ float g_s    [(size_t)BATCH * LQ * KT];     // 306 MB scores/weights
__device__ float g_att  [(size_t)BATCH * LQ * DIMN];   // 134 MB

// ---------------------------------------------------------------------------
// f32x2 packed-FMA helpers (sm_100+/sm_103a)
// ---------------------------------------------------------------------------
__device__ __forceinline__ unsigned long long pack_dup(float x) {
    unsigned long long r;
    asm("mov.b64 %0, {%1, %1};" : "=l"(r) : "f"(x));
    return r;
}
__device__ __forceinline__ void unpack2(unsigned long long v, float& x, float& y) {
    asm("mov.b64 {%0, %1}, %2;" : "=f"(x), "=f"(y) : "l"(v));
}
__device__ __forceinline__ void fma2(unsigned long long& d,
                                     unsigned long long a,
                                     unsigned long long b) {
    asm("fma.rn.f32x2 %0, %1, %2, %0;" : "+l"(d) : "l"(a), "l"(b));
}

// ---------------------------------------------------------------------------
// Tiled GEMM, 128x128 tile, BK=8, 256 threads, 8x8 per thread (as 8x4 f32x2).
//   TRANSB=true :  C[M,N] = alpha * A[M,K] @ B[N,K]^T + bias
//   TRANSB=false:  C[M,N] = alpha * A[M,K] @ B[K,N]   + bias
// A rows (M) must be a multiple of 128 and K a multiple of 8 (true for all
// launches here). N edge handled by predication. blockIdx.z selects batch via
// the element strides sA/sB/sC.
// Inner loop uses packed fma.rn.f32x2: A is stored DUPLICATED in smem so each
// LDS.64 yields {a,a}; B pairs alias directly out of LDS.128.
// ---------------------------------------------------------------------------
#define BM  128
#define BN  128
#define BKK 8

template<bool TRANSB>
__global__ __launch_bounds__(256, 2)
void gemm_kernel(const float* __restrict__ Ag, const float* __restrict__ Bg,
                 const float* __restrict__ bias, float* __restrict__ Cg,
                 int M, int N, int K, float alpha,
                 long long sA, long long sB, long long sC)
{
    const float* A = Ag + (long long)blockIdx.z * sA;
    const float* B = Bg + (long long)blockIdx.z * sB;
    float*       C = Cg + (long long)blockIdx.z * sC;

    __shared__ float AsD[BKK][2 * BM + 4];  // duplicated A, stride 260 (8B-aligned rows)
    __shared__ float Bs [BKK][BN + 4];      // stride 132 (16B-aligned rows)

    const int tid  = threadIdx.x;
    const int tx   = tid & 15;       // 0..15  -> N micro-tile
    const int ty   = tid >> 4;       // 0..15  -> M micro-tile
    const int row0 = blockIdx.y * BM;
    const int col0 = blockIdx.x * BN;

    // global->smem load mapping (NT path: both A and B are [rows, K])
    const int lr = tid >> 1;         // 0..127 row within tile
    const int lc = (tid & 1) << 2;   // k offset {0,4}
    // NN path B mapping: [K, N] tile of 8 x 128
    const int bkr  = tid >> 5;           // 0..7  k row
    const int bcol = (tid & 31) << 2;    // 0..124 col (float4)

    unsigned long long acc[8][4];
#pragma unroll
    for (int i = 0; i < 8; i++)
#pragma unroll
        for (int j = 0; j < 4; j++) acc[i][j] = 0ull;

    for (int k0 = 0; k0 < K; k0 += BKK) {
        // ---- global loads into registers
        float4 av = *reinterpret_cast<const float4*>(
            &A[(long long)(row0 + lr) * K + (k0 + lc)]);
        float4 bv = make_float4(0.f, 0.f, 0.f, 0.f);
        if (TRANSB) {
            if (col0 + lr < N)
                bv = *reinterpret_cast<const float4*>(
                    &B[(long long)(col0 + lr) * K + (k0 + lc)]);
        } else {
            if (col0 + bcol < N)
                bv = *reinterpret_cast<const float4*>(
                    &B[(long long)(k0 + bkr) * N + (col0 + bcol)]);
        }

        __syncthreads();  // previous tile fully consumed

        // ---- store A duplicated: AsD[k][2r] = AsD[k][2r+1] = a
        *reinterpret_cast<unsigned long long*>(&AsD[lc + 0][2 * lr]) = pack_dup(av.x);
        *reinterpret_cast<unsigned long long*>(&AsD[lc + 1][2 * lr]) = pack_dup(av.y);
        *reinterpret_cast<unsigned long long*>(&AsD[lc + 2][2 * lr]) = pack_dup(av.z);
        *reinterpret_cast<unsigned long long*>(&AsD[lc + 3][2 * lr]) = pack_dup(av.w);
        if (TRANSB) {
            Bs[lc + 0][lr] = bv.x;
            Bs[lc + 1][lr] = bv.y;
            Bs[lc + 2][lr] = bv.z;
            Bs[lc + 3][lr] = bv.w;
        } else {
            *reinterpret_cast<float4*>(&Bs[bkr][bcol]) = bv;
        }

        __syncthreads();

        // ---- compute
#pragma unroll
        for (int kk = 0; kk < BKK; kk++) {
            unsigned long long aa[8];
#pragma unroll
            for (int i = 0; i < 8; i++)
                aa[i] = *reinterpret_cast<const unsigned long long*>(
                    &AsD[kk][ty * 16 + 2 * i]);
            double2 b01 = *reinterpret_cast<const double2*>(&Bs[kk][tx * 8]);
            double2 b23 = *reinterpret_cast<const double2*>(&Bs[kk][tx * 8 + 4]);
            unsigned long long bb[4];
            bb[0] = __double_as_longlong(b01.x);
            bb[1] = __double_as_longlong(b01.y);
            bb[2] = __double_as_longlong(b23.x);
            bb[3] = __double_as_longlong(b23.y);
#pragma unroll
            for (int i = 0; i < 8; i++)
#pragma unroll
                for (int j = 0; j < 4; j++)
                    fma2(acc[i][j], aa[i], bb[j]);
        }
    }

    // ---- epilogue
#pragma unroll
    for (int i = 0; i < 8; i++) {
        const int row = row0 + ty * 8 + i;
#pragma unroll
        for (int j = 0; j < 4; j++) {
            const int col = col0 + tx * 8 + 2 * j;
            if (col < N) {  // N is always even -> pair check collapses
                float x, y;
                unpack2(acc[i][j], x, y);
                x *= alpha; y *= alpha;
                if (bias) { x += bias[col]; y += bias[col + 1]; }
                *reinterpret_cast<float2*>(&C[(long long)row * N + col]) =
                    make_float2(x, y);
            }
        }
    }
}

// ---------------------------------------------------------------------------
// Copy cached K/V into the front of the full K/V buffers
// ---------------------------------------------------------------------------
__global__ void copy_cached_kernel(const float* __restrict__ ck,
                                   const float* __restrict__ cv)
{
    const int per   = KC * DIMN / 4;          // float4 per batch = 294912
    const int total = BATCH * per;            // 1179648
    int idx = blockIdx.x * blockDim.x + threadIdx.x;
    if (idx >= total) return;
    int b = idx / per;
    int r = idx - b * per;
    long long dst = (long long)b * (KT * DIMN / 4) + r;
    reinterpret_cast<float4*>(g_kfull)[dst] = reinterpret_cast<const float4*>(ck)[idx];
    reinterpret_cast<float4*>(g_vfull)[dst] = reinterpret_cast<const float4*>(cv)[idx];
}

// ---------------------------------------------------------------------------
// Row softmax with analytic causal mask: row q sees columns [0, 576+q+1),
// masked columns are written as 0 so the following NN GEMM is plain dense.
// ---------------------------------------------------------------------------
__global__ void softmax_kernel(float* __restrict__ S, float scale)
{
    const int q = blockIdx.x;   // 0..LQ-1
    const int b = blockIdx.y;
    float* row = S + ((long long)b * LQ + q) * KT;
    const int valid = KC + q + 1;     // <= KT
    const int tid = threadIdx.x;
    __shared__ float red[256];

    // pass 1: max of scaled scores
    float m = -1e30f;
    for (int c = tid; c < valid; c += 256) m = fmaxf(m, row[c] * scale);
    red[tid] = m;
    __syncthreads();
    for (int s = 128; s > 0; s >>= 1) {
        if (tid < s) red[tid] = fmaxf(red[tid], red[tid + s]);
        __syncthreads();
    }
    m = red[0];
    __syncthreads();

    // pass 2: sum of exp
    float sum = 0.f;
    for (int c = tid; c < valid; c += 256) sum += expf(row[c] * scale - m);
    red[tid] = sum;
    __syncthreads();
    for (int s = 128; s > 0; s >>= 1) {
        if (tid < s) red[tid] += red[tid + s];
        __syncthreads();
    }
    const float inv = 1.f / red[0];
    __syncthreads();

    // pass 3: write normalized weights, zeros beyond the causal frontier
    for (int c = tid; c < KT; c += 256)
        row[c] = (c < valid) ? expf(row[c] * scale - m) * inv : 0.f;
}

// ---------------------------------------------------------------------------
// kernel_launch — graph-capturable, allocation-free
// ---------------------------------------------------------------------------
extern "C" void kernel_launch(void* const* d_in, const int* in_sizes, int n_in,
                              void* d_out, int out_size)
{
    const float* chunk    = (const float*)d_in[0];
    const float* cached_k = (const float*)d_in[1];
    const float* cached_v = (const float*)d_in[2];
    // d_in[3] = cached_positions, then (possibly) total_seen — both unused:
    // every cached position < every new query position, so the mask is
    // analytic. Locate Wq robustly by size in case scalar inputs are skipped.
    int wi = 3;
    while (wi < n_in && in_sizes[wi] != DIMN * DIMN) wi++;
    const float* Wq = (const float*)d_in[wi + 0];
    const float* bq = (const float*)d_in[wi + 1];
    const float* Wk = (const float*)d_in[wi + 2];
    const float* bk = (const float*)d_in[wi + 3];
    const float* Wv = (const float*)d_in[wi + 4];
    const float* bv = (const float*)d_in[wi + 5];
    const float* Wo = (const float*)d_in[wi + 6];
    const float* bo = (const float*)d_in[wi + 7];
    float* out = (float*)d_out;

    float *pq, *pkf, *pvf, *ps, *patt;
    cudaGetSymbolAddress((void**)&pq,   g_q);
    cudaGetSymbolAddress((void**)&pkf,  g_kfull);
    cudaGetSymbolAddress((void**)&pvf,  g_vfull);
    cudaGetSymbolAddress((void**)&ps,   g_s);
    cudaGetSymbolAddress((void**)&patt, g_att);

    const float scale = (float)(1.0 / sqrt((double)DIMN));
    const dim3 blk(256);

    // 1) cached K/V -> front of full K/V
    copy_cached_kernel<<<(BATCH * KC * DIMN / 4 + 255) / 256, 256>>>(cached_k, cached_v);

    // 2) Q projection: [B*L, D] @ Wq^T + bq (batch folded into M)
    gemm_kernel<true><<<dim3(DIMN / BN, (BATCH * LQ) / BM, 1), blk>>>(
        chunk, Wq, bq, pq, BATCH * LQ, DIMN, DIMN, 1.f, 0, 0, 0);

    // 3) K projection -> rows [KC, KT) of g_kfull, per batch
    gemm_kernel<true><<<dim3(DIMN / BN, LQ / BM, BATCH), blk>>>(
        chunk, Wk, bk, pkf + (long long)KC * DIMN, LQ, DIMN, DIMN, 1.f,
        (long long)LQ * DIMN, 0, (long long)KT * DIMN);

    // 4) V projection -> rows [KC, KT) of g_vfull
    gemm_kernel<true><<<dim3(DIMN / BN, LQ / BM, BATCH), blk>>>(
        chunk, Wv, bv, pvf + (long long)KC * DIMN, LQ, DIMN, DIMN, 1.f,
        (long long)LQ * DIMN, 0, (long long)KT * DIMN);

    // 5) S = q @ k_full^T  (scale folded into softmax)
    gemm_kernel<true><<<dim3((KT + BN - 1) / BN, LQ / BM, BATCH), blk>>>(
        pq, pkf, nullptr, ps, LQ, KT, DIMN, 1.f,
        (long long)LQ * DIMN, (long long)KT * DIMN, (long long)LQ * KT);

    // 6) masked softmax (writes zeros beyond the causal frontier)
    softmax_kernel<<<dim3(LQ, BATCH), 256>>>(ps, scale);

    // 7) attended = W @ v_full  (NN)
    gemm_kernel<false><<<dim3(DIMN / BN, LQ / BM, BATCH), blk>>>(
        ps, pvf, nullptr, patt, LQ, DIMN, KT, 1.f,
        (long long)LQ * KT, (long long)KT * DIMN, (long long)LQ * DIMN);

    // 8) output projection: attended @ Wo^T + bo (batch folded into M)
    gemm_kernel<true><<<dim3(DIMN / BN, (BATCH * LQ) / BM, 1), blk>>>(
        patt, Wo, bo, out, BATCH * LQ, DIMN, DIMN, 1.f, 0, 0, 0);
}

// round 4
// speedup vs baseline: 2.6441x; 2.6441x over previous
#include <cuda_runtime.h>
#include <cuda_bf16.h>
#include <math.h>
#include <stdint.h>

#define DIMN 2048
#define BATCH 4
#define LQ    4096
#define KC    576
#define KT    4672          // KC + LQ
#define KTP   4864          // padded N for the S GEMM (38*128)

typedef __nv_bfloat16 bf16;

// ---------------------------------------------------------------------------
// Scratch (__device__ globals — zero-initialized; K rows [KT,KTP) stay 0)
// ---------------------------------------------------------------------------
__device__ bf16 g_ch [(size_t)BATCH*LQ*DIMN];
__device__ bf16 g_cl [(size_t)BATCH*LQ*DIMN];
__device__ bf16 g_wqh[(size_t)DIMN*DIMN], g_wql[(size_t)DIMN*DIMN];
__device__ bf16 g_wkh[(size_t)DIMN*DIMN], g_wkl[(size_t)DIMN*DIMN];
__device__ bf16 g_wvh[(size_t)DIMN*DIMN], g_wvl[(size_t)DIMN*DIMN];
__device__ bf16 g_woh[(size_t)DIMN*DIMN], g_wol[(size_t)DIMN*DIMN];
__device__ bf16 g_qh [(size_t)BATCH*LQ*DIMN],  g_ql[(size_t)BATCH*LQ*DIMN];
__device__ bf16 g_kh [(size_t)BATCH*KTP*DIMN], g_kl[(size_t)BATCH*KTP*DIMN];
__device__ bf16 g_vh [(size_t)BATCH*DIMN*KT],  g_vl[(size_t)BATCH*DIMN*KT]; // V^T [b][d][kt]
__device__ float g_s [(size_t)BATCH*LQ*KTP];
__device__ bf16 g_ph [(size_t)BATCH*LQ*KT],    g_pl[(size_t)BATCH*LQ*KT];
__device__ bf16 g_ah [(size_t)BATCH*LQ*DIMN],  g_al[(size_t)BATCH*LQ*DIMN];

// ---------------------------------------------------------------------------
// helpers
// ---------------------------------------------------------------------------
__device__ __forceinline__ uint32_t s2u(const void* p) {
    uint32_t a;
    asm("{ .reg .u64 t; cvta.to.shared.u64 t, %1; cvt.u32.u64 %0, t; }" : "=r"(a) : "l"(p));
    return a;
}
__device__ __forceinline__ void cpa16(uint32_t d, const void* s) {
    asm volatile("cp.async.cg.shared.global [%0], [%1], 16;" :: "r"(d), "l"(s));
}
#define CP_COMMIT() asm volatile("cp.async.commit_group;" ::: "memory")
#define CP_WAIT1()  asm volatile("cp.async.wait_group 1;" ::: "memory")

#define LDSM4(r, a) \
    asm volatile("ldmatrix.sync.aligned.m8n8.x4.shared.b16 {%0,%1,%2,%3}, [%4];" \
                 : "=r"((r)[0]), "=r"((r)[1]), "=r"((r)[2]), "=r"((r)[3]) : "r"(a))

__device__ __forceinline__ void mma16816(float* d, const uint32_t* a,
                                         uint32_t b0, uint32_t b1) {
    asm volatile(
        "mma.sync.aligned.m16n8k16.row.col.f32.bf16.bf16.f32 "
        "{%0,%1,%2,%3}, {%4,%5,%6,%7}, {%8,%9}, {%0,%1,%2,%3};"
        : "+f"(d[0]), "+f"(d[1]), "+f"(d[2]), "+f"(d[3])
        : "r"(a[0]), "r"(a[1]), "r"(a[2]), "r"(a[3]), "r"(b0), "r"(b1));
}

__device__ __forceinline__ void split2(float x0, float x1, uint32_t& h, uint32_t& l) {
    __nv_bfloat162 hp = __floats2bfloat162_rn(x0, x1);
    __nv_bfloat162 lp = __floats2bfloat162_rn(x0 - __low2float(hp), x1 - __high2float(hp));
    h = *reinterpret_cast<uint32_t*>(&hp);
    l = *reinterpret_cast<uint32_t*>(&lp);
}

// ---------------------------------------------------------------------------
// mma.sync GEMM: C tile 128x128, BK=32, 3-stage cp.async pipeline.
// 3-pass split: Ah·Bh + Al·Bh + Ah·Bl, fp32 accum. A[M,K], B[N,K] row-major.
// MODE: 0 fp32 out, 1 split-bf16 out. BIASM: 0 none, 1 bias[col], 2 bias[row]
// ---------------------------------------------------------------------------
#define BMT 128
#define BNT 128
#define BKT 32
#define APAD 40                         // bf16 row stride (32 + 8) -> 80B
#define STAGE_ELE (2 * 128 * APAD)      // A+B per stage (bf16 elems) = 10240
#define SMEM_MMA (3 * STAGE_ELE * 2)    // 61440 bytes

template<int MODE, int BIASM>
__global__ __launch_bounds__(256, 2)
void gemm_mma(const bf16* __restrict__ Ah, const bf16* __restrict__ Al,
              const bf16* __restrict__ Bh, const bf16* __restrict__ Bl,
              const float* __restrict__ bias,
              float* __restrict__ Cf, bf16* __restrict__ Ch, bf16* __restrict__ Cl,
              int K, int lda, int ldb, int ldc,
              long long sA, long long sB, long long sC)
{
    extern __shared__ bf16 sm[];
    const uint32_t smb = s2u(sm);
    const int tid  = threadIdx.x;
    const int lane = tid & 31, warp = tid >> 5;
    const int wm = warp & 1, wn = warp >> 1;    // warp grid 2 (M) x 4 (N)
    const size_t zA = (size_t)blockIdx.z * sA;
    const size_t zB = (size_t)blockIdx.z * sB;
    const size_t zC = (size_t)blockIdx.z * sC;
    const int row0 = blockIdx.y * BMT;
    const int col0 = blockIdx.x * BNT;

    const int kchunks = K / BKT;
    const int T = 3 * kchunks;

    // cp.async mapping: thread covers A/B rows (tid>>2) and (tid>>2)+64
    const int lrow = tid >> 2;
    const int lcol = (tid & 3) * 8;

    auto issue = [&](int it, int st) {
        const int p  = it / kchunks;
        const int kc = it - p * kchunks;
        const bf16* Asrc = ((p == 1) ? Al : Ah) + zA + (size_t)(row0 + lrow) * lda + (size_t)kc * BKT + lcol;
        const bf16* Bsrc = ((p == 2) ? Bl : Bh) + zB + (size_t)(col0 + lrow) * ldb + (size_t)kc * BKT + lcol;
        const uint32_t ab = smb + st * (STAGE_ELE * 2);
        const uint32_t bb = ab + 128 * APAD * 2;
        cpa16(ab + (lrow * APAD + lcol) * 2,        Asrc);
        cpa16(ab + ((lrow + 64) * APAD + lcol) * 2, Asrc + (size_t)64 * lda);
        cpa16(bb + (lrow * APAD + lcol) * 2,        Bsrc);
        cpa16(bb + ((lrow + 64) * APAD + lcol) * 2, Bsrc + (size_t)64 * ldb);
    };

    float acc[4][4][4];
#pragma unroll
    for (int i = 0; i < 4; i++)
#pragma unroll
        for (int j = 0; j < 4; j++)
#pragma unroll
            for (int e = 0; e < 4; e++) acc[i][j][e] = 0.f;

    // ldmatrix per-thread address components
    const int am = wm * 64 + (lane & 15);   // + mt*16
    const int ak = (lane >> 4) * 8;         // k-offset within 16
    const int bn = wn * 32 + (lane & 15);   // + pr*16

    issue(0, 0); CP_COMMIT();
    issue(1, 1); CP_COMMIT();

    for (int it = 0; it < T; ++it) {
        const int st = it - (it / 3) * 3;
        CP_WAIT1();
        __syncthreads();
        if (it + 2 < T) issue(it + 2, (it + 2) % 3);
        CP_COMMIT();

        const uint32_t ab = smb + st * (STAGE_ELE * 2);
        const uint32_t bb = ab + 128 * APAD * 2;
#pragma unroll
        for (int ks = 0; ks < 2; ks++) {
            uint32_t af[4][4], bfr[2][4];
#pragma unroll
            for (int mt = 0; mt < 4; mt++)
                LDSM4(af[mt], ab + (((am + mt * 16) * APAD) + ks * 16 + ak) * 2);
#pragma unroll
            for (int pr = 0; pr < 2; pr++)
                LDSM4(bfr[pr], bb + (((bn + pr * 16) * APAD) + ks * 16 + ak) * 2);
#pragma unroll
            for (int mt = 0; mt < 4; mt++)
#pragma unroll
                for (int nt = 0; nt < 4; nt++)
                    mma16816(acc[mt][nt], af[mt],
                             bfr[nt >> 1][nt & 1], bfr[nt >> 1][(nt & 1) + 2]);
        }
    }

    // epilogue
    const int crow = lane >> 2;
    const int ccol = (lane & 3) * 2;
#pragma unroll
    for (int mt = 0; mt < 4; mt++) {
        const size_t r0g = (size_t)row0 + wm * 64 + mt * 16 + crow;
#pragma unroll
        for (int nt = 0; nt < 4; nt++) {
            const int cg = col0 + wn * 32 + nt * 8 + ccol;
            float v0 = acc[mt][nt][0], v1 = acc[mt][nt][1];
            float v2 = acc[mt][nt][2], v3 = acc[mt][nt][3];
            if (BIASM == 1) {
                const float b0 = bias[cg], b1 = bias[cg + 1];
                v0 += b0; v1 += b1; v2 += b0; v3 += b1;
            }
            if (BIASM == 2) {
                const float b0 = bias[r0g], b1 = bias[r0g + 8];
                v0 += b0; v1 += b0; v2 += b1; v3 += b1;
            }
            if (MODE == 0) {
                *reinterpret_cast<float2*>(&Cf[zC + r0g * ldc + cg])       = make_float2(v0, v1);
                *reinterpret_cast<float2*>(&Cf[zC + (r0g + 8) * ldc + cg]) = make_float2(v2, v3);
            } else {
                uint32_t h, l;
                split2(v0, v1, h, l);
                *reinterpret_cast<uint32_t*>(&Ch[zC + r0g * ldc + cg]) = h;
                *reinterpret_cast<uint32_t*>(&Cl[zC + r0g * ldc + cg]) = l;
                split2(v2, v3, h, l);
                *reinterpret_cast<uint32_t*>(&Ch[zC + (r0g + 8) * ldc + cg]) = h;
                *reinterpret_cast<uint32_t*>(&Cl[zC + (r0g + 8) * ldc + cg]) = l;
            }
        }
    }
}

// ---------------------------------------------------------------------------
// Elementwise fp32 -> split bf16
// ---------------------------------------------------------------------------
__global__ void split_kernel(const float* __restrict__ src, bf16* __restrict__ h,
                             bf16* __restrict__ l, size_t n4)
{
    size_t i = (size_t)blockIdx.x * blockDim.x + threadIdx.x;
    if (i >= n4) return;
    float4 v = reinterpret_cast<const float4*>(src)[i];
    uint32_t h0, h1, l0, l1;
    split2(v.x, v.y, h0, l0);
    split2(v.z, v.w, h1, l1);
    reinterpret_cast<uint2*>(h)[i] = make_uint2(h0, h1);
    reinterpret_cast<uint2*>(l)[i] = make_uint2(l0, l1);
}

__global__ void cachek_kernel(const float* __restrict__ ck)
{
    const size_t per = (size_t)KC * DIMN / 4;
    size_t i = (size_t)blockIdx.x * blockDim.x + threadIdx.x;
    if (i >= BATCH * per) return;
    size_t b = i / per, r = i - b * per;
    float4 v = reinterpret_cast<const float4*>(ck)[i];
    uint32_t h0, h1, l0, l1;
    split2(v.x, v.y, h0, l0);
    split2(v.z, v.w, h1, l1);
    size_t dst = b * ((size_t)KTP * DIMN / 4) + r;
    reinterpret_cast<uint2*>(g_kh)[dst] = make_uint2(h0, h1);
    reinterpret_cast<uint2*>(g_kl)[dst] = make_uint2(l0, l1);
}

// cached_v [B,KC,D] -> transposed split into g_vh/g_vl [B,D,KT] cols [0,KC)
__global__ void cachev_kernel(const float* __restrict__ cv)
{
    __shared__ float t[32][33];
    const int b = blockIdx.z;
    const int r0 = blockIdx.x * 32;   // kc
    const int c0 = blockIdx.y * 32;   // d
    const int tx = threadIdx.x, ty0 = threadIdx.y;
#pragma unroll
    for (int s = 0; s < 4; s++) {
        int ty = ty0 + s * 8;
        t[ty][tx] = cv[((size_t)b * KC + r0 + ty) * DIMN + c0 + tx];
    }
    __syncthreads();
#pragma unroll
    for (int s = 0; s < 4; s++) {
        int ty = ty0 + s * 8;
        float x = t[tx][ty];
        bf16 h = __float2bfloat16(x);
        bf16 lo = __float2bfloat16(x - __bfloat162float(h));
        size_t o = ((size_t)b * DIMN + c0 + ty) * KT + r0 + tx;
        g_vh[o] = h;
        g_vl[o] = lo;
    }
}

// ---------------------------------------------------------------------------
// Masked softmax: row q sees [0, KC+q+1); emits split-bf16 weights (0 beyond)
// ---------------------------------------------------------------------------
__global__ void softmax_kernel(const float* __restrict__ S, bf16* __restrict__ Wh,
                               bf16* __restrict__ Wl, float scale)
{
    const int q = blockIdx.x, b = blockIdx.y;
    const float* row = S + ((size_t)b * LQ + q) * KTP;
    bf16* wh = Wh + ((size_t)b * LQ + q) * KT;
    bf16* wl = Wl + ((size_t)b * LQ + q) * KT;
    const int valid = KC + q + 1;
    const int tid = threadIdx.x;
    __shared__ float red[256];

    float m = -1e30f;
    for (int c = tid; c < valid; c += 256) m = fmaxf(m, row[c] * scale);
    red[tid] = m; __syncthreads();
    for (int s = 128; s > 0; s >>= 1) { if (tid < s) red[tid] = fmaxf(red[tid], red[tid + s]); __syncthreads(); }
    m = red[0]; __syncthreads();

    float sum = 0.f;
    for (int c = tid; c < valid; c += 256) sum += expf(row[c] * scale - m);
    red[tid] = sum; __syncthreads();
    for (int s = 128; s > 0; s >>= 1) { if (tid < s) red[tid] += red[tid + s]; __syncthreads(); }
    const float inv = 1.f / red[0];
    __syncthreads();

    for (int c = tid; c < KT; c += 256) {
        float w = (c < valid) ? expf(row[c] * scale - m) * inv : 0.f;
        bf16 h = __float2bfloat16(w);
        wh[c] = h;
        wl[c] = __float2bfloat16(w - __bfloat162float(h));
    }
}

// ---------------------------------------------------------------------------
// kernel_launch
// ---------------------------------------------------------------------------
extern "C" void kernel_launch(void* const* d_in, const int* in_sizes, int n_in,
                              void* d_out, int out_size)
{
    const float* chunk    = (const float*)d_in[0];
    const float* cached_k = (const float*)d_in[1];
    const float* cached_v = (const float*)d_in[2];
    int wi = 3;
    while (wi < n_in && in_sizes[wi] != DIMN * DIMN) wi++;
    const float* Wq = (const float*)d_in[wi + 0];
    const float* bq = (const float*)d_in[wi + 1];
    const float* Wk = (const float*)d_in[wi + 2];
    const float* bk = (const float*)d_in[wi + 3];
    const float* Wv = (const float*)d_in[wi + 4];
    const float* bv = (const float*)d_in[wi + 5];
    const float* Wo = (const float*)d_in[wi + 6];
    const float* bo = (const float*)d_in[wi + 7];
    float* out = (float*)d_out;

    bf16 *ch, *cl, *wqh, *wql, *wkh, *wkl, *wvh, *wvl, *woh, *wol;
    bf16 *qh, *ql, *kh, *kl, *vh, *vl, *phh, *pll, *ahh, *all;
    float* s;
    cudaGetSymbolAddress((void**)&ch, g_ch);   cudaGetSymbolAddress((void**)&cl, g_cl);
    cudaGetSymbolAddress((void**)&wqh, g_wqh); cudaGetSymbolAddress((void**)&wql, g_wql);
    cudaGetSymbolAddress((void**)&wkh, g_wkh); cudaGetSymbolAddress((void**)&wkl, g_wkl);
    cudaGetSymbolAddress((void**)&wvh, g_wvh); cudaGetSymbolAddress((void**)&wvl, g_wvl);
    cudaGetSymbolAddress((void**)&woh, g_woh); cudaGetSymbolAddress((void**)&wol, g_wol);
    cudaGetSymbolAddress((void**)&qh, g_qh);   cudaGetSymbolAddress((void**)&ql, g_ql);
    cudaGetSymbolAddress((void**)&kh, g_kh);   cudaGetSymbolAddress((void**)&kl, g_kl);
    cudaGetSymbolAddress((void**)&vh, g_vh);   cudaGetSymbolAddress((void**)&vl, g_vl);
    cudaGetSymbolAddress((void**)&s, g_s);
    cudaGetSymbolAddress((void**)&phh, g_ph);  cudaGetSymbolAddress((void**)&pll, g_pl);
    cudaGetSymbolAddress((void**)&ahh, g_ah);  cudaGetSymbolAddress((void**)&all, g_al);

    cudaFuncSetAttribute(gemm_mma<1,1>, cudaFuncAttributeMaxDynamicSharedMemorySize, SMEM_MMA);
    cudaFuncSetAttribute(gemm_mma<1,2>, cudaFuncAttributeMaxDynamicSharedMemorySize, SMEM_MMA);
    cudaFuncSetAttribute(gemm_mma<0,0>, cudaFuncAttributeMaxDynamicSharedMemorySize, SMEM_MMA);
    cudaFuncSetAttribute(gemm_mma<1,0>, cudaFuncAttributeMaxDynamicSharedMemorySize, SMEM_MMA);
    cudaFuncSetAttribute(gemm_mma<0,1>, cudaFuncAttributeMaxDynamicSharedMemorySize, SMEM_MMA);

    const float scale = (float)(1.0 / sqrt((double)DIMN));

    // input conversions
    {
        size_t n4 = (size_t)BATCH * LQ * DIMN / 4;
        split_kernel<<<(unsigned)((n4 + 255) / 256), 256>>>(chunk, ch, cl, n4);
        size_t w4 = (size_t)DIMN * DIMN / 4;
        unsigned wg = (unsigned)((w4 + 255) / 256);
        split_kernel<<<wg, 256>>>(Wq, wqh, wql, w4);
        split_kernel<<<wg, 256>>>(Wk, wkh, wkl, w4);
        split_kernel<<<wg, 256>>>(Wv, wvh, wvl, w4);
        split_kernel<<<wg, 256>>>(Wo, woh, wol, w4);
        size_t ck4 = (size_t)BATCH * KC * DIMN / 4;
        cachek_kernel<<<(unsigned)((ck4 + 255) / 256), 256>>>(cached_k);
        cachev_kernel<<<dim3(KC / 32, DIMN / 32, BATCH), dim3(32, 8)>>>(cached_v);
    }

    // Q projection: [B*L,D] @ Wq^T + bq -> split
    gemm_mma<1,1><<<dim3(DIMN / BNT, (BATCH * LQ) / BMT, 1), 256, SMEM_MMA>>>(
        ch, cl, wqh, wql, bq, nullptr, qh, ql,
        DIMN, DIMN, DIMN, DIMN, 0, 0, 0);

    // K projection -> k_full rows [KC, KT) per batch (row stride KTP)
    gemm_mma<1,1><<<dim3(DIMN / BNT, LQ / BMT, BATCH), 256, SMEM_MMA>>>(
        ch, cl, wkh, wkl, bk, nullptr, kh + (size_t)KC * DIMN, kl + (size_t)KC * DIMN,
        DIMN, DIMN, DIMN, DIMN,
        (long long)LQ * DIMN, 0, (long long)KTP * DIMN);

    // V^T projection: newV^T = Wv @ chunk^T + bv(row) -> vT cols [KC, KT)
    gemm_mma<1,2><<<dim3(LQ / BNT, DIMN / BMT, BATCH), 256, SMEM_MMA>>>(
        wvh, wvl, ch, cl, bv, nullptr, vh + KC, vl + KC,
        DIMN, DIMN, DIMN, KT,
        0, (long long)LQ * DIMN, (long long)DIMN * KT);

    // S = q @ k_full^T (fp32 out; scale folded into softmax)
    gemm_mma<0,0><<<dim3(KTP / BNT, LQ / BMT, BATCH), 256, SMEM_MMA>>>(
        qh, ql, kh, kl, nullptr, s, nullptr, nullptr,
        DIMN, DIMN, DIMN, KTP,
        (long long)LQ * DIMN, (long long)KTP * DIMN, (long long)LQ * KTP);

    // masked softmax -> split weights
    softmax_kernel<<<dim3(LQ, BATCH), 256>>>(s, phh, pll, scale);

    // attended = W @ V (NT against V^T): A=[LQ,KT], B=[DIMN,KT]
    gemm_mma<1,0><<<dim3(DIMN / BNT, LQ / BMT, BATCH), 256, SMEM_MMA>>>(
        phh, pll, vh, vl, nullptr, nullptr, ahh, all,
        KT, KT, KT, DIMN,
        (long long)LQ * KT, (long long)DIMN * KT, (long long)LQ * DIMN);

    // output projection: attended @ Wo^T + bo -> fp32 out
    gemm_mma<0,1><<<dim3(DIMN / BNT, (BATCH * LQ) / BMT, 1), 256, SMEM_MMA>>>(
        ahh, all, woh, wol, bo, out, nullptr, nullptr,
        DIMN, DIMN, DIMN, DIMN, 0, 0, 0);
}

// round 5
// speedup vs baseline: 3.7187x; 1.4064x over previous
#include <cuda_runtime.h>
#include <cuda_bf16.h>
#include <math.h>
#include <stdint.h>

#define DIMN 2048
#define BATCH 4
#define LQ    4096
#define KC    576
#define KT    4672          // KC + LQ
#define KTP   4864          // padded N for the S GEMM (38*128)

typedef __nv_bfloat16 bf16;

// ---------------------------------------------------------------------------
// Scratch (__device__ globals — zero-initialized; K rows [KT,KTP) stay 0)
// ---------------------------------------------------------------------------
__device__ bf16 g_ch [(size_t)BATCH*LQ*DIMN];
__device__ bf16 g_cl [(size_t)BATCH*LQ*DIMN];
__device__ bf16 g_wqh[(size_t)DIMN*DIMN], g_wql[(size_t)DIMN*DIMN];
__device__ bf16 g_wkh[(size_t)DIMN*DIMN], g_wkl[(size_t)DIMN*DIMN];
__device__ bf16 g_wvh[(size_t)DIMN*DIMN], g_wvl[(size_t)DIMN*DIMN];
__device__ bf16 g_woh[(size_t)DIMN*DIMN], g_wol[(size_t)DIMN*DIMN];
__device__ bf16 g_qh [(size_t)BATCH*LQ*DIMN],  g_ql[(size_t)BATCH*LQ*DIMN];
__device__ bf16 g_kh [(size_t)BATCH*KTP*DIMN], g_kl[(size_t)BATCH*KTP*DIMN];
__device__ bf16 g_vh [(size_t)BATCH*DIMN*KT],  g_vl[(size_t)BATCH*DIMN*KT]; // V^T [b][d][kt]
__device__ float g_s [(size_t)BATCH*LQ*KTP];
__device__ bf16 g_ph [(size_t)BATCH*LQ*KT],    g_pl[(size_t)BATCH*LQ*KT];
__device__ bf16 g_ah [(size_t)BATCH*LQ*DIMN],  g_al[(size_t)BATCH*LQ*DIMN];

// ---------------------------------------------------------------------------
// helpers
// ---------------------------------------------------------------------------
__device__ __forceinline__ uint32_t s2u(const void* p) {
    uint32_t a;
    asm("{ .reg .u64 t; cvta.to.shared.u64 t, %1; cvt.u32.u64 %0, t; }" : "=r"(a) : "l"(p));
    return a;
}
__device__ __forceinline__ void cpa16(uint32_t d, const void* s) {
    asm volatile("cp.async.cg.shared.global [%0], [%1], 16;" :: "r"(d), "l"(s));
}
#define CP_COMMIT() asm volatile("cp.async.commit_group;" ::: "memory")
#define CP_WAIT1()  asm volatile("cp.async.wait_group 1;" ::: "memory")
#define CP_WAIT0()  asm volatile("cp.async.wait_group 0;" ::: "memory")

#define LDSM4(r, a) \
    asm volatile("ldmatrix.sync.aligned.m8n8.x4.shared.b16 {%0,%1,%2,%3}, [%4];" \
                 : "=r"((r)[0]), "=r"((r)[1]), "=r"((r)[2]), "=r"((r)[3]) : "r"(a))

__device__ __forceinline__ void mma16816(float* d, const uint32_t* a,
                                         uint32_t b0, uint32_t b1) {
    asm volatile(
        "mma.sync.aligned.m16n8k16.row.col.f32.bf16.bf16.f32 "
        "{%0,%1,%2,%3}, {%4,%5,%6,%7}, {%8,%9}, {%0,%1,%2,%3};"
        : "+f"(d[0]), "+f"(d[1]), "+f"(d[2]), "+f"(d[3])
        : "r"(a[0]), "r"(a[1]), "r"(a[2]), "r"(a[3]), "r"(b0), "r"(b1));
}

__device__ __forceinline__ void split2(float x0, float x1, uint32_t& h, uint32_t& l) {
    __nv_bfloat162 hp = __floats2bfloat162_rn(x0, x1);
    __nv_bfloat162 lp = __floats2bfloat162_rn(x0 - __low2float(hp), x1 - __high2float(hp));
    h = *reinterpret_cast<uint32_t*>(&hp);
    l = *reinterpret_cast<uint32_t*>(&lp);
}

// ---------------------------------------------------------------------------
// Fused-split mma.sync GEMM: C tile 128x128, BK=32, 2-stage cp.async pipeline.
// One K sweep loading Ah,Al,Bh,Bl; per k-step mma groups Ah·Bh + Ah·Bl + Al·Bh.
// A[M,K], B[N,K] row-major (NT). fp32 accum.
// MODE: 0 fp32 out, 1 split-bf16 out. BIASM: 0 none, 1 bias[col], 2 bias[row]
// TRI:  0 none, 1 = skip block if col0 >= KC+row0+BMT (S GEMM),
//       2 = clamp K loop to KC+row0+BMT (AV GEMM; weights are 0 beyond)
// ---------------------------------------------------------------------------
#define BMT 128
#define BNT 128
#define BKT 32
#define APAD 40                          // bf16 row stride (32+8) -> 80B
#define TILE_B (128 * APAD * 2)          // 10240 bytes per tile
#define STAGE_B (4 * TILE_B)             // Ah|Al|Bh|Bl = 40960
#define SMEM_MMA (2 * STAGE_B)           // 81920 bytes

template<int MODE, int BIASM, int TRI>
__global__ __launch_bounds__(256, 2)
void gemm_mma(const bf16* __restrict__ Ah, const bf16* __restrict__ Al,
              const bf16* __restrict__ Bh, const bf16* __restrict__ Bl,
              const float* __restrict__ bias,
              float* __restrict__ Cf, bf16* __restrict__ Ch, bf16* __restrict__ Cl,
              int K, int lda, int ldb, int ldc,
              long long sA, long long sB, long long sC)
{
    const int row0 = blockIdx.y * BMT;
    const int col0 = blockIdx.x * BNT;
    if (TRI == 1 && col0 >= KC + row0 + BMT) return;   // fully-masked S tile

    extern __shared__ bf16 sm[];
    const uint32_t smb = s2u(sm);
    const int tid  = threadIdx.x;
    const int lane = tid & 31, warp = tid >> 5;
    const int wm = warp & 1, wn = warp >> 1;    // warp grid 2 (M) x 4 (N)
    const size_t zA = (size_t)blockIdx.z * sA;
    const size_t zB = (size_t)blockIdx.z * sB;
    const size_t zC = (size_t)blockIdx.z * sC;

    int kchunks = K / BKT;
    if (TRI == 2) {
        int lim = (KC + row0 + BMT) / BKT;      // multiple of 32 by construction
        if (lim < kchunks) kchunks = lim;
    }

    // cp.async mapping: rows (tid>>2) and (tid>>2)+64, 16B chunk (tid&3)*8
    const int lrow = tid >> 2;
    const int lcol = (tid & 3) * 8;
    const uint32_t o1 = (lrow * APAD + lcol) * 2;
    const uint32_t o2 = ((lrow + 64) * APAD + lcol) * 2;

    auto issue = [&](int kc, int st) {
        const size_t ao = zA + (size_t)(row0 + lrow) * lda + (size_t)kc * BKT + lcol;
        const size_t bo = zB + (size_t)(col0 + lrow) * ldb + (size_t)kc * BKT + lcol;
        const uint32_t base = smb + st * STAGE_B;
        cpa16(base + o1,              Ah + ao);
        cpa16(base + o2,              Ah + ao + (size_t)64 * lda);
        cpa16(base + TILE_B + o1,     Al + ao);
        cpa16(base + TILE_B + o2,     Al + ao + (size_t)64 * lda);
        cpa16(base + 2*TILE_B + o1,   Bh + bo);
        cpa16(base + 2*TILE_B + o2,   Bh + bo + (size_t)64 * ldb);
        cpa16(base + 3*TILE_B + o1,   Bl + bo);
        cpa16(base + 3*TILE_B + o2,   Bl + bo + (size_t)64 * ldb);
    };

    float acc[4][4][4];
#pragma unroll
    for (int i = 0; i < 4; i++)
#pragma unroll
        for (int j = 0; j < 4; j++)
#pragma unroll
            for (int e = 0; e < 4; e++) acc[i][j][e] = 0.f;

    // ldmatrix per-thread address components
    const int am = wm * 64 + (lane & 15);
    const int ak = (lane >> 4) * 8;
    const int bn = wn * 32 + (lane & 15);

    issue(0, 0); CP_COMMIT();

    for (int kc = 0; kc < kchunks; ++kc) {
        const int st = kc & 1;
        if (kc + 1 < kchunks) { issue(kc + 1, (kc + 1) & 1); CP_COMMIT(); CP_WAIT1(); }
        else                  { CP_WAIT0(); }
        __syncthreads();

        const uint32_t ah_ = smb + st * STAGE_B;
        const uint32_t al_ = ah_ + TILE_B;
        const uint32_t bh_ = ah_ + 2 * TILE_B;
        const uint32_t bl_ = ah_ + 3 * TILE_B;
#pragma unroll
        for (int ks = 0; ks < 2; ks++) {
            uint32_t af[4][4], bh[2][4], bl[2][4];
#pragma unroll
            for (int mt = 0; mt < 4; mt++)
                LDSM4(af[mt], ah_ + (((am + mt * 16) * APAD) + ks * 16 + ak) * 2);
#pragma unroll
            for (int pr = 0; pr < 2; pr++) {
                LDSM4(bh[pr], bh_ + (((bn + pr * 16) * APAD) + ks * 16 + ak) * 2);
                LDSM4(bl[pr], bl_ + (((bn + pr * 16) * APAD) + ks * 16 + ak) * 2);
            }
            // Ah·Bh and Ah·Bl
#pragma unroll
            for (int mt = 0; mt < 4; mt++)
#pragma unroll
                for (int nt = 0; nt < 4; nt++) {
                    mma16816(acc[mt][nt], af[mt],
                             bh[nt >> 1][nt & 1], bh[nt >> 1][(nt & 1) + 2]);
                    mma16816(acc[mt][nt], af[mt],
                             bl[nt >> 1][nt & 1], bl[nt >> 1][(nt & 1) + 2]);
                }
            // Al·Bh (reuse af registers)
#pragma unroll
            for (int mt = 0; mt < 4; mt++)
                LDSM4(af[mt], al_ + (((am + mt * 16) * APAD) + ks * 16 + ak) * 2);
#pragma unroll
            for (int mt = 0; mt < 4; mt++)
#pragma unroll
                for (int nt = 0; nt < 4; nt++)
                    mma16816(acc[mt][nt], af[mt],
                             bh[nt >> 1][nt & 1], bh[nt >> 1][(nt & 1) + 2]);
        }
        __syncthreads();   // stage consumed before it is refilled
    }

    // epilogue
    const int crow = lane >> 2;
    const int ccol = (lane & 3) * 2;
#pragma unroll
    for (int mt = 0; mt < 4; mt++) {
        const size_t r0g = (size_t)row0 + wm * 64 + mt * 16 + crow;
#pragma unroll
        for (int nt = 0; nt < 4; nt++) {
            const int cg = col0 + wn * 32 + nt * 8 + ccol;
            float v0 = acc[mt][nt][0], v1 = acc[mt][nt][1];
            float v2 = acc[mt][nt][2], v3 = acc[mt][nt][3];
            if (BIASM == 1) {
                const float b0 = bias[cg], b1 = bias[cg + 1];
                v0 += b0; v1 += b1; v2 += b0; v3 += b1;
            }
            if (BIASM == 2) {
                const float b0 = bias[r0g], b1 = bias[r0g + 8];
                v0 += b0; v1 += b0; v2 += b1; v3 += b1;
            }
            if (MODE == 0) {
                *reinterpret_cast<float2*>(&Cf[zC + r0g * ldc + cg])       = make_float2(v0, v1);
                *reinterpret_cast<float2*>(&Cf[zC + (r0g + 8) * ldc + cg]) = make_float2(v2, v3);
            } else {
                uint32_t h, l;
                split2(v0, v1, h, l);
                *reinterpret_cast<uint32_t*>(&Ch[zC + r0g * ldc + cg]) = h;
                *reinterpret_cast<uint32_t*>(&Cl[zC + r0g * ldc + cg]) = l;
                split2(v2, v3, h, l);
                *reinterpret_cast<uint32_t*>(&Ch[zC + (r0g + 8) * ldc + cg]) = h;
                *reinterpret_cast<uint32_t*>(&Cl[zC + (r0g + 8) * ldc + cg]) = l;
            }
        }
    }
}

// ---------------------------------------------------------------------------
// Elementwise fp32 -> split bf16
// ---------------------------------------------------------------------------
__global__ void split_kernel(const float* __restrict__ src, bf16* __restrict__ h,
                             bf16* __restrict__ l, size_t n4)
{
    size_t i = (size_t)blockIdx.x * blockDim.x + threadIdx.x;
    if (i >= n4) return;
    float4 v = reinterpret_cast<const float4*>(src)[i];
    uint32_t h0, h1, l0, l1;
    split2(v.x, v.y, h0, l0);
    split2(v.z, v.w, h1, l1);
    reinterpret_cast<uint2*>(h)[i] = make_uint2(h0, h1);
    reinterpret_cast<uint2*>(l)[i] = make_uint2(l0, l1);
}

__global__ void cachek_kernel(const float* __restrict__ ck)
{
    const size_t per = (size_t)KC * DIMN / 4;
    size_t i = (size_t)blockIdx.x * blockDim.x + threadIdx.x;
    if (i >= BATCH * per) return;
    size_t b = i / per, r = i - b * per;
    float4 v = reinterpret_cast<const float4*>(ck)[i];
    uint32_t h0, h1, l0, l1;
    split2(v.x, v.y, h0, l0);
    split2(v.z, v.w, h1, l1);
    size_t dst = b * ((size_t)KTP * DIMN / 4) + r;
    reinterpret_cast<uint2*>(g_kh)[dst] = make_uint2(h0, h1);
    reinterpret_cast<uint2*>(g_kl)[dst] = make_uint2(l0, l1);
}

// cached_v [B,KC,D] -> transposed split into g_vh/g_vl [B,D,KT] cols [0,KC)
__global__ void cachev_kernel(const float* __restrict__ cv)
{
    __shared__ float t[32][33];
    const int b = blockIdx.z;
    const int r0 = blockIdx.x * 32;   // kc
    const int c0 = blockIdx.y * 32;   // d
    const int tx = threadIdx.x, ty0 = threadIdx.y;
#pragma unroll
    for (int s = 0; s < 4; s++) {
        int ty = ty0 + s * 8;
        t[ty][tx] = cv[((size_t)b * KC + r0 + ty) * DIMN + c0 + tx];
    }
    __syncthreads();
#pragma unroll
    for (int s = 0; s < 4; s++) {
        int ty = ty0 + s * 8;
        float x = t[tx][ty];
        bf16 h = __float2bfloat16(x);
        bf16 lo = __float2bfloat16(x - __bfloat162float(h));
        size_t o = ((size_t)b * DIMN + c0 + ty) * KT + r0 + tx;
        g_vh[o] = h;
        g_vl[o] = lo;
    }
}

// ---------------------------------------------------------------------------
// Masked softmax: row q sees [0, KC+q+1); emits split-bf16 weights (0 beyond).
// Exp values cached in smem (one exp pass).
// ---------------------------------------------------------------------------
__global__ void softmax_kernel(const float* __restrict__ S, bf16* __restrict__ Wh,
                               bf16* __restrict__ Wl, float scale)
{
    __shared__ float sbuf[KT];
    __shared__ float red[256];
    const int q = blockIdx.x, b = blockIdx.y;
    const float* row = S + ((size_t)b * LQ + q) * KTP;
    bf16* wh = Wh + ((size_t)b * LQ + q) * KT;
    bf16* wl = Wl + ((size_t)b * LQ + q) * KT;
    const int valid = KC + q + 1;
    const int tid = threadIdx.x;

    float m = -1e30f;
    for (int c = tid; c < valid; c += 256) m = fmaxf(m, row[c] * scale);
    red[tid] = m; __syncthreads();
    for (int s = 128; s > 0; s >>= 1) { if (tid < s) red[tid] = fmaxf(red[tid], red[tid + s]); __syncthreads(); }
    m = red[0]; __syncthreads();

    float sum = 0.f;
    for (int c = tid; c < valid; c += 256) {
        float e = __expf(row[c] * scale - m);
        sbuf[c] = e;
        sum += e;
    }
    red[tid] = sum; __syncthreads();
    for (int s = 128; s > 0; s >>= 1) { if (tid < s) red[tid] += red[tid + s]; __syncthreads(); }
    const float inv = 1.f / red[0];
    __syncthreads();

    for (int c = tid; c < KT; c += 256) {
        float w = (c < valid) ? sbuf[c] * inv : 0.f;
        bf16 h = __float2bfloat16(w);
        wh[c] = h;
        wl[c] = __float2bfloat16(w - __bfloat162float(h));
    }
}

// ---------------------------------------------------------------------------
// kernel_launch
// ---------------------------------------------------------------------------
extern "C" void kernel_launch(void* const* d_in, const int* in_sizes, int n_in,
                              void* d_out, int out_size)
{
    const float* chunk    = (const float*)d_in[0];
    const float* cached_k = (const float*)d_in[1];
    const float* cached_v = (const float*)d_in[2];
    int wi = 3;
    while (wi < n_in && in_sizes[wi] != DIMN * DIMN) wi++;
    const float* Wq = (const float*)d_in[wi + 0];
    const float* bq = (const float*)d_in[wi + 1];
    const float* Wk = (const float*)d_in[wi + 2];
    const float* bk = (const float*)d_in[wi + 3];
    const float* Wv = (const float*)d_in[wi + 4];
    const float* bv = (const float*)d_in[wi + 5];
    const float* Wo = (const float*)d_in[wi + 6];
    const float* bo = (const float*)d_in[wi + 7];
    float* out = (float*)d_out;

    bf16 *ch, *cl, *wqh, *wql, *wkh, *wkl, *wvh, *wvl, *woh, *wol;
    bf16 *qh, *ql, *kh, *kl, *vh, *vl, *phh, *pll, *ahh, *all;
    float* s;
    cudaGetSymbolAddress((void**)&ch, g_ch);   cudaGetSymbolAddress((void**)&cl, g_cl);
    cudaGetSymbolAddress((void**)&wqh, g_wqh); cudaGetSymbolAddress((void**)&wql, g_wql);
    cudaGetSymbolAddress((void**)&wkh, g_wkh); cudaGetSymbolAddress((void**)&wkl, g_wkl);
    cudaGetSymbolAddress((void**)&wvh, g_wvh); cudaGetSymbolAddress((void**)&wvl, g_wvl);
    cudaGetSymbolAddress((void**)&woh, g_woh); cudaGetSymbolAddress((void**)&wol, g_wol);
    cudaGetSymbolAddress((void**)&qh, g_qh);   cudaGetSymbolAddress((void**)&ql, g_ql);
    cudaGetSymbolAddress((void**)&kh, g_kh);   cudaGetSymbolAddress((void**)&kl, g_kl);
    cudaGetSymbolAddress((void**)&vh, g_vh);   cudaGetSymbolAddress((void**)&vl, g_vl);
    cudaGetSymbolAddress((void**)&s, g_s);
    cudaGetSymbolAddress((void**)&phh, g_ph);  cudaGetSymbolAddress((void**)&pll, g_pl);
    cudaGetSymbolAddress((void**)&ahh, g_ah);  cudaGetSymbolAddress((void**)&all, g_al);

    cudaFuncSetAttribute(gemm_mma<1,1,0>, cudaFuncAttributeMaxDynamicSharedMemorySize, SMEM_MMA);
    cudaFuncSetAttribute(gemm_mma<1,2,0>, cudaFuncAttributeMaxDynamicSharedMemorySize, SMEM_MMA);
    cudaFuncSetAttribute(gemm_mma<0,0,1>, cudaFuncAttributeMaxDynamicSharedMemorySize, SMEM_MMA);
    cudaFuncSetAttribute(gemm_mma<1,0,2>, cudaFuncAttributeMaxDynamicSharedMemorySize, SMEM_MMA);
    cudaFuncSetAttribute(gemm_mma<0,1,0>, cudaFuncAttributeMaxDynamicSharedMemorySize, SMEM_MMA);

    const float scale = (float)(1.0 / sqrt((double)DIMN));

    // input conversions
    {
        size_t n4 = (size_t)BATCH * LQ * DIMN / 4;
        split_kernel<<<(unsigned)((n4 + 255) / 256), 256>>>(chunk, ch, cl, n4);
        size_t w4 = (size_t)DIMN * DIMN / 4;
        unsigned wg = (unsigned)((w4 + 255) / 256);
        split_kernel<<<wg, 256>>>(Wq, wqh, wql, w4);
        split_kernel<<<wg, 256>>>(Wk, wkh, wkl, w4);
        split_kernel<<<wg, 256>>>(Wv, wvh, wvl, w4);
        split_kernel<<<wg, 256>>>(Wo, woh, wol, w4);
        size_t ck4 = (size_t)BATCH * KC * DIMN / 4;
        cachek_kernel<<<(unsigned)((ck4 + 255) / 256), 256>>>(cached_k);
        cachev_kernel<<<dim3(KC / 32, DIMN / 32, BATCH), dim3(32, 8)>>>(cached_v);
    }

    // Q projection: [B*L,D] @ Wq^T + bq -> split
    gemm_mma<1,1,0><<<dim3(DIMN / BNT, (BATCH * LQ) / BMT, 1), 256, SMEM_MMA>>>(
        ch, cl, wqh, wql, bq, nullptr, qh, ql,
        DIMN, DIMN, DIMN, DIMN, 0, 0, 0);

    // K projection -> k_full rows [KC, KT) per batch (row stride KTP)
    gemm_mma<1,1,0><<<dim3(DIMN / BNT, LQ / BMT, BATCH), 256, SMEM_MMA>>>(
        ch, cl, wkh, wkl, bk, nullptr, kh + (size_t)KC * DIMN, kl + (size_t)KC * DIMN,
        DIMN, DIMN, DIMN, DIMN,
        (long long)LQ * DIMN, 0, (long long)KTP * DIMN);

    // V^T projection: newV^T = Wv @ chunk^T + bv(row) -> vT cols [KC, KT)
    gemm_mma<1,2,0><<<dim3(LQ / BNT, DIMN / BMT, BATCH), 256, SMEM_MMA>>>(
        wvh, wvl, ch, cl, bv, nullptr, vh + KC, vl + KC,
        DIMN, DIMN, DIMN, KT,
        0, (long long)LQ * DIMN, (long long)DIMN * KT);

    // S = q @ k_full^T (fp32 out; scale folded into softmax; masked tiles skipped)
    gemm_mma<0,0,1><<<dim3(KTP / BNT, LQ / BMT, BATCH), 256, SMEM_MMA>>>(
        qh, ql, kh, kl, nullptr, s, nullptr, nullptr,
        DIMN, DIMN, DIMN, KTP,
        (long long)LQ * DIMN, (long long)KTP * DIMN, (long long)LQ * KTP);

    // masked softmax -> split weights
    softmax_kernel<<<dim3(LQ, BATCH), 256>>>(s, phh, pll, scale);

    // attended = P @ V (NT against V^T), K loop clamped to causal frontier
    gemm_mma<1,0,2><<<dim3(DIMN / BNT, LQ / BMT, BATCH), 256, SMEM_MMA>>>(
        phh, pll, vh, vl, nullptr, nullptr, ahh, all,
        KT, KT, KT, DIMN,
        (long long)LQ * KT, (long long)DIMN * KT, (long long)LQ * DIMN);

    // output projection: attended @ Wo^T + bo -> fp32 out
    gemm_mma<0,1,0><<<dim3(DIMN / BNT, (BATCH * LQ) / BMT, 1), 256, SMEM_MMA>>>(
        ahh, all, woh, wol, bo, out, nullptr, nullptr,
        DIMN, DIMN, DIMN, DIMN, 0, 0, 0);
}

// round 6
// speedup vs baseline: 3.7832x; 1.0173x over previous
#include <cuda_runtime.h>
#include <cuda_bf16.h>
#include <math.h>
#include <stdint.h>

#define DIMN 2048
#define BATCH 4
#define LQ    4096
#define KC    576
#define KT    4672          // KC + LQ
#define KTP   4864          // padded N for the S GEMM (38*128)

typedef __nv_bfloat16 bf16;

// ---------------------------------------------------------------------------
// Scratch (__device__ globals — zero-initialized; K rows [KT,KTP) stay 0)
// ---------------------------------------------------------------------------
__device__ bf16 g_ch [(size_t)BATCH*LQ*DIMN];
__device__ bf16 g_cl [(size_t)BATCH*LQ*DIMN];
__device__ bf16 g_wqh[(size_t)DIMN*DIMN], g_wql[(size_t)DIMN*DIMN];
__device__ bf16 g_wkh[(size_t)DIMN*DIMN], g_wkl[(size_t)DIMN*DIMN];
__device__ bf16 g_wvh[(size_t)DIMN*DIMN], g_wvl[(size_t)DIMN*DIMN];
__device__ bf16 g_woh[(size_t)DIMN*DIMN], g_wol[(size_t)DIMN*DIMN];
__device__ bf16 g_qh [(size_t)BATCH*LQ*DIMN],  g_ql[(size_t)BATCH*LQ*DIMN];
__device__ bf16 g_kh [(size_t)BATCH*KTP*DIMN], g_kl[(size_t)BATCH*KTP*DIMN];
__device__ bf16 g_vh [(size_t)BATCH*DIMN*KT],  g_vl[(size_t)BATCH*DIMN*KT]; // V^T [b][d][kt]
__device__ float g_s [(size_t)BATCH*LQ*KTP];
__device__ bf16 g_ph [(size_t)BATCH*LQ*KT],    g_pl[(size_t)BATCH*LQ*KT];
__device__ bf16 g_ah [(size_t)BATCH*LQ*DIMN],  g_al[(size_t)BATCH*LQ*DIMN];

// ---------------------------------------------------------------------------
// helpers
// ---------------------------------------------------------------------------
__device__ __forceinline__ uint32_t s2u(const void* p) {
    uint32_t a;
    asm("{ .reg .u64 t; cvta.to.shared.u64 t, %1; cvt.u32.u64 %0, t; }" : "=r"(a) : "l"(p));
    return a;
}
__device__ __forceinline__ void cpa16(uint32_t d, const void* s) {
    asm volatile("cp.async.cg.shared.global [%0], [%1], 16;" :: "r"(d), "l"(s));
}
#define CP_COMMIT() asm volatile("cp.async.commit_group;" ::: "memory")
#define CP_WAIT1()  asm volatile("cp.async.wait_group 1;" ::: "memory")
#define CP_WAIT0()  asm volatile("cp.async.wait_group 0;" ::: "memory")

#define LDSM4(r, a) \
    asm volatile("ldmatrix.sync.aligned.m8n8.x4.shared.b16 {%0,%1,%2,%3}, [%4];" \
                 : "=r"((r)[0]), "=r"((r)[1]), "=r"((r)[2]), "=r"((r)[3]) : "r"(a))

__device__ __forceinline__ void mma16816(float* d, const uint32_t* a,
                                         uint32_t b0, uint32_t b1) {
    asm volatile(
        "mma.sync.aligned.m16n8k16.row.col.f32.bf16.bf16.f32 "
        "{%0,%1,%2,%3}, {%4,%5,%6,%7}, {%8,%9}, {%0,%1,%2,%3};"
        : "+f"(d[0]), "+f"(d[1]), "+f"(d[2]), "+f"(d[3])
        : "r"(a[0]), "r"(a[1]), "r"(a[2]), "r"(a[3]), "r"(b0), "r"(b1));
}

__device__ __forceinline__ void split2(float x0, float x1, uint32_t& h, uint32_t& l) {
    __nv_bfloat162 hp = __floats2bfloat162_rn(x0, x1);
    __nv_bfloat162 lp = __floats2bfloat162_rn(x0 - __low2float(hp), x1 - __high2float(hp));
    h = *reinterpret_cast<uint32_t*>(&hp);
    l = *reinterpret_cast<uint32_t*>(&lp);
}

// ---------------------------------------------------------------------------
// Fused-split mma.sync GEMM: C tile 128x128, BK=32, 2-stage cp.async pipeline.
// One K sweep loading Ah,Al,Bh,Bl; per k-step mma groups Ah·Bh + Ah·Bl + Al·Bh,
// with LDSM interleaved between groups to keep the shared pipe off the
// critical path.
// A[M,K], B[N,K] row-major (NT). fp32 accum.
// MODE: 0 fp32 out, 1 split-bf16 out. BIASM: 0 none, 1 bias[col], 2 bias[row]
// TRI:  0 none, 1 = skip block if col0 >= KC+row0+BMT (S GEMM),
//       2 = clamp K loop to KC+row0+BMT (AV GEMM; heavy rows scheduled first)
// ---------------------------------------------------------------------------
#define BMT 128
#define BNT 128
#define BKT 32
#define APAD 40                          // bf16 row stride (32+8) -> 80B
#define TILE_B (128 * APAD * 2)          // 10240 bytes per tile
#define STAGE_B (4 * TILE_B)             // Ah|Al|Bh|Bl = 40960
#define SMEM_MMA (2 * STAGE_B)           // 81920 bytes

template<int MODE, int BIASM, int TRI>
__global__ __launch_bounds__(256, 2)
void gemm_mma(const bf16* __restrict__ Ah, const bf16* __restrict__ Al,
              const bf16* __restrict__ Bh, const bf16* __restrict__ Bl,
              const float* __restrict__ bias,
              float* __restrict__ Cf, bf16* __restrict__ Ch, bf16* __restrict__ Cl,
              int K, int lda, int ldb, int ldc,
              long long sA, long long sB, long long sC)
{
    // TRI==2: reverse row order so the heaviest (longest-K) CTAs start first
    const int row0 = (TRI == 2 ? (int)(gridDim.y - 1 - blockIdx.y) : (int)blockIdx.y) * BMT;
    const int col0 = blockIdx.x * BNT;
    if (TRI == 1 && col0 >= KC + row0 + BMT) return;   // fully-masked S tile

    extern __shared__ bf16 sm[];
    const uint32_t smb = s2u(sm);
    const int tid  = threadIdx.x;
    const int lane = tid & 31, warp = tid >> 5;
    const int wm = warp & 1, wn = warp >> 1;    // warp grid 2 (M) x 4 (N)
    const size_t zA = (size_t)blockIdx.z * sA;
    const size_t zB = (size_t)blockIdx.z * sB;
    const size_t zC = (size_t)blockIdx.z * sC;

    int kchunks = K / BKT;
    if (TRI == 2) {
        int lim = (KC + row0 + BMT) / BKT;      // multiple of 32 by construction
        if (lim < kchunks) kchunks = lim;
    }

    // cp.async mapping: rows (tid>>2) and (tid>>2)+64, 16B chunk (tid&3)*8
    const int lrow = tid >> 2;
    const int lcol = (tid & 3) * 8;
    const uint32_t o1 = (lrow * APAD + lcol) * 2;
    const uint32_t o2 = ((lrow + 64) * APAD + lcol) * 2;

    auto issue = [&](int kc, int st) {
        const size_t ao = zA + (size_t)(row0 + lrow) * lda + (size_t)kc * BKT + lcol;
        const size_t bo = zB + (size_t)(col0 + lrow) * ldb + (size_t)kc * BKT + lcol;
        const uint32_t base = smb + st * STAGE_B;
        cpa16(base + o1,              Ah + ao);
        cpa16(base + o2,              Ah + ao + (size_t)64 * lda);
        cpa16(base + TILE_B + o1,     Al + ao);
        cpa16(base + TILE_B + o2,     Al + ao + (size_t)64 * lda);
        cpa16(base + 2*TILE_B + o1,   Bh + bo);
        cpa16(base + 2*TILE_B + o2,   Bh + bo + (size_t)64 * ldb);
        cpa16(base + 3*TILE_B + o1,   Bl + bo);
        cpa16(base + 3*TILE_B + o2,   Bl + bo + (size_t)64 * ldb);
    };

    float acc[4][4][4];
#pragma unroll
    for (int i = 0; i < 4; i++)
#pragma unroll
        for (int j = 0; j < 4; j++)
#pragma unroll
            for (int e = 0; e < 4; e++) acc[i][j][e] = 0.f;

    // ldmatrix per-thread address components
    const int am = wm * 64 + (lane & 15);
    const int ak = (lane >> 4) * 8;
    const int bn = wn * 32 + (lane & 15);

    issue(0, 0); CP_COMMIT();

    for (int kc = 0; kc < kchunks; ++kc) {
        const int st = kc & 1;
        if (kc + 1 < kchunks) { issue(kc + 1, (kc + 1) & 1); CP_COMMIT(); CP_WAIT1(); }
        else                  { CP_WAIT0(); }
        __syncthreads();

        const uint32_t ah_ = smb + st * STAGE_B;
        const uint32_t al_ = ah_ + TILE_B;
        const uint32_t bh_ = ah_ + 2 * TILE_B;
        const uint32_t bl_ = ah_ + 3 * TILE_B;
#pragma unroll
        for (int ks = 0; ks < 2; ks++) {
            uint32_t af[4][4], bh[2][4], bl[2][4];
            // load A(hi) + B(hi), start the hh group
#pragma unroll
            for (int mt = 0; mt < 4; mt++)
                LDSM4(af[mt], ah_ + (((am + mt * 16) * APAD) + ks * 16 + ak) * 2);
#pragma unroll
            for (int pr = 0; pr < 2; pr++)
                LDSM4(bh[pr], bh_ + (((bn + pr * 16) * APAD) + ks * 16 + ak) * 2);
#pragma unroll
            for (int mt = 0; mt < 4; mt++)
#pragma unroll
                for (int nt = 0; nt < 4; nt++)
                    mma16816(acc[mt][nt], af[mt],
                             bh[nt >> 1][nt & 1], bh[nt >> 1][(nt & 1) + 2]);
            // load B(lo) while hh drains, then hl group
#pragma unroll
            for (int pr = 0; pr < 2; pr++)
                LDSM4(bl[pr], bl_ + (((bn + pr * 16) * APAD) + ks * 16 + ak) * 2);
#pragma unroll
            for (int mt = 0; mt < 4; mt++)
#pragma unroll
                for (int nt = 0; nt < 4; nt++)
                    mma16816(acc[mt][nt], af[mt],
                             bl[nt >> 1][nt & 1], bl[nt >> 1][(nt & 1) + 2]);
            // load A(lo) (reusing af regs) while hl drains, then lh group
#pragma unroll
            for (int mt = 0; mt < 4; mt++)
                LDSM4(af[mt], al_ + (((am + mt * 16) * APAD) + ks * 16 + ak) * 2);
#pragma unroll
            for (int mt = 0; mt < 4; mt++)
#pragma unroll
                for (int nt = 0; nt < 4; nt++)
                    mma16816(acc[mt][nt], af[mt],
                             bh[nt >> 1][nt & 1], bh[nt >> 1][(nt & 1) + 2]);
        }
        __syncthreads();   // stage consumed before it is refilled
    }

    // epilogue
    const int crow = lane >> 2;
    const int ccol = (lane & 3) * 2;
#pragma unroll
    for (int mt = 0; mt < 4; mt++) {
        const size_t r0g = (size_t)row0 + wm * 64 + mt * 16 + crow;
#pragma unroll
        for (int nt = 0; nt < 4; nt++) {
            const int cg = col0 + wn * 32 + nt * 8 + ccol;
            float v0 = acc[mt][nt][0], v1 = acc[mt][nt][1];
            float v2 = acc[mt][nt][2], v3 = acc[mt][nt][3];
            if (BIASM == 1) {
                const float b0 = bias[cg], b1 = bias[cg + 1];
                v0 += b0; v1 += b1; v2 += b0; v3 += b1;
            }
            if (BIASM == 2) {
                const float b0 = bias[r0g], b1 = bias[r0g + 8];
                v0 += b0; v1 += b0; v2 += b1; v3 += b1;
            }
            if (MODE == 0) {
                *reinterpret_cast<float2*>(&Cf[zC + r0g * ldc + cg])       = make_float2(v0, v1);
                *reinterpret_cast<float2*>(&Cf[zC + (r0g + 8) * ldc + cg]) = make_float2(v2, v3);
            } else {
                uint32_t h, l;
                split2(v0, v1, h, l);
                *reinterpret_cast<uint32_t*>(&Ch[zC + r0g * ldc + cg]) = h;
                *reinterpret_cast<uint32_t*>(&Cl[zC + r0g * ldc + cg]) = l;
                split2(v2, v3, h, l);
                *reinterpret_cast<uint32_t*>(&Ch[zC + (r0g + 8) * ldc + cg]) = h;
                *reinterpret_cast<uint32_t*>(&Cl[zC + (r0g + 8) * ldc + cg]) = l;
            }
        }
    }
}

// ---------------------------------------------------------------------------
// Elementwise fp32 -> split bf16
// ---------------------------------------------------------------------------
__global__ void split_kernel(const float* __restrict__ src, bf16* __restrict__ h,
                             bf16* __restrict__ l, size_t n4)
{
    size_t i = (size_t)blockIdx.x * blockDim.x + threadIdx.x;
    if (i >= n4) return;
    float4 v = reinterpret_cast<const float4*>(src)[i];
    uint32_t h0, h1, l0, l1;
    split2(v.x, v.y, h0, l0);
    split2(v.z, v.w, h1, l1);
    reinterpret_cast<uint2*>(h)[i] = make_uint2(h0, h1);
    reinterpret_cast<uint2*>(l)[i] = make_uint2(l0, l1);
}

__global__ void cachek_kernel(const float* __restrict__ ck)
{
    const size_t per = (size_t)KC * DIMN / 4;
    size_t i = (size_t)blockIdx.x * blockDim.x + threadIdx.x;
    if (i >= BATCH * per) return;
    size_t b = i / per, r = i - b * per;
    float4 v = reinterpret_cast<const float4*>(ck)[i];
    uint32_t h0, h1, l0, l1;
    split2(v.x, v.y, h0, l0);
    split2(v.z, v.w, h1, l1);
    size_t dst = b * ((size_t)KTP * DIMN / 4) + r;
    reinterpret_cast<uint2*>(g_kh)[dst] = make_uint2(h0, h1);
    reinterpret_cast<uint2*>(g_kl)[dst] = make_uint2(l0, l1);
}

// cached_v [B,KC,D] -> transposed split into g_vh/g_vl [B,D,KT] cols [0,KC)
__global__ void cachev_kernel(const float* __restrict__ cv)
{
    __shared__ float t[32][33];
    const int b = blockIdx.z;
    const int r0 = blockIdx.x * 32;   // kc
    const int c0 = blockIdx.y * 32;   // d
    const int tx = threadIdx.x, ty0 = threadIdx.y;
#pragma unroll
    for (int s = 0; s < 4; s++) {
        int ty = ty0 + s * 8;
        t[ty][tx] = cv[((size_t)b * KC + r0 + ty) * DIMN + c0 + tx];
    }
    __syncthreads();
#pragma unroll
    for (int s = 0; s < 4; s++) {
        int ty = ty0 + s * 8;
        float x = t[tx][ty];
        bf16 h = __float2bfloat16(x);
        bf16 lo = __float2bfloat16(x - __bfloat162float(h));
        size_t o = ((size_t)b * DIMN + c0 + ty) * KT + r0 + tx;
        g_vh[o] = h;
        g_vl[o] = lo;
    }
}

// ---------------------------------------------------------------------------
// Masked softmax: row q sees [0, KC+q+1); emits split-bf16 weights (0 beyond).
// Exp values cached in smem (one exp pass).
// ---------------------------------------------------------------------------
__global__ void softmax_kernel(const float* __restrict__ S, bf16* __restrict__ Wh,
                               bf16* __restrict__ Wl, float scale)
{
    __shared__ float sbuf[KT];
    __shared__ float red[256];
    const int q = blockIdx.x, b = blockIdx.y;
    const float* row = S + ((size_t)b * LQ + q) * KTP;
    bf16* wh = Wh + ((size_t)b * LQ + q) * KT;
    bf16* wl = Wl + ((size_t)b * LQ + q) * KT;
    const int valid = KC + q + 1;
    const int tid = threadIdx.x;

    float m = -1e30f;
    for (int c = tid; c < valid; c += 256) m = fmaxf(m, row[c] * scale);
    red[tid] = m; __syncthreads();
    for (int s = 128; s > 0; s >>= 1) { if (tid < s) red[tid] = fmaxf(red[tid], red[tid + s]); __syncthreads(); }
    m = red[0]; __syncthreads();

    float sum = 0.f;
    for (int c = tid; c < valid; c += 256) {
        float e = __expf(row[c] * scale - m);
        sbuf[c] = e;
        sum += e;
    }
    red[tid] = sum; __syncthreads();
    for (int s = 128; s > 0; s >>= 1) { if (tid < s) red[tid] += red[tid + s]; __syncthreads(); }
    const float inv = 1.f / red[0];
    __syncthreads();

    for (int c = tid; c < KT; c += 256) {
        float w = (c < valid) ? sbuf[c] * inv : 0.f;
        bf16 h = __float2bfloat16(w);
        wh[c] = h;
        wl[c] = __float2bfloat16(w - __bfloat162float(h));
    }
}

// ---------------------------------------------------------------------------
// kernel_launch
// ---------------------------------------------------------------------------
extern "C" void kernel_launch(void* const* d_in, const int* in_sizes, int n_in,
                              void* d_out, int out_size)
{
    const float* chunk    = (const float*)d_in[0];
    const float* cached_k = (const float*)d_in[1];
    const float* cached_v = (const float*)d_in[2];
    int wi = 3;
    while (wi < n_in && in_sizes[wi] != DIMN * DIMN) wi++;
    const float* Wq = (const float*)d_in[wi + 0];
    const float* bq = (const float*)d_in[wi + 1];
    const float* Wk = (const float*)d_in[wi + 2];
    const float* bk = (const float*)d_in[wi + 3];
    const float* Wv = (const float*)d_in[wi + 4];
    const float* bv = (const float*)d_in[wi + 5];
    const float* Wo = (const float*)d_in[wi + 6];
    const float* bo = (const float*)d_in[wi + 7];
    float* out = (float*)d_out;

    bf16 *ch, *cl, *wqh, *wql, *wkh, *wkl, *wvh, *wvl, *woh, *wol;
    bf16 *qh, *ql, *kh, *kl, *vh, *vl, *phh, *pll, *ahh, *all;
    float* s;
    cudaGetSymbolAddress((void**)&ch, g_ch);   cudaGetSymbolAddress((void**)&cl, g_cl);
    cudaGetSymbolAddress((void**)&wqh, g_wqh); cudaGetSymbolAddress((void**)&wql, g_wql);
    cudaGetSymbolAddress((void**)&wkh, g_wkh); cudaGetSymbolAddress((void**)&wkl, g_wkl);
    cudaGetSymbolAddress((void**)&wvh, g_wvh); cudaGetSymbolAddress((void**)&wvl, g_wvl);
    cudaGetSymbolAddress((void**)&woh, g_woh); cudaGetSymbolAddress((void**)&wol, g_wol);
    cudaGetSymbolAddress((void**)&qh, g_qh);   cudaGetSymbolAddress((void**)&ql, g_ql);
    cudaGetSymbolAddress((void**)&kh, g_kh);   cudaGetSymbolAddress((void**)&kl, g_kl);
    cudaGetSymbolAddress((void**)&vh, g_vh);   cudaGetSymbolAddress((void**)&vl, g_vl);
    cudaGetSymbolAddress((void**)&s, g_s);
    cudaGetSymbolAddress((void**)&phh, g_ph);  cudaGetSymbolAddress((void**)&pll, g_pl);
    cudaGetSymbolAddress((void**)&ahh, g_ah);  cudaGetSymbolAddress((void**)&all, g_al);

    cudaFuncSetAttribute(gemm_mma<1,1,0>, cudaFuncAttributeMaxDynamicSharedMemorySize, SMEM_MMA);
    cudaFuncSetAttribute(gemm_mma<1,2,0>, cudaFuncAttributeMaxDynamicSharedMemorySize, SMEM_MMA);
    cudaFuncSetAttribute(gemm_mma<0,0,1>, cudaFuncAttributeMaxDynamicSharedMemorySize, SMEM_MMA);
    cudaFuncSetAttribute(gemm_mma<1,0,2>, cudaFuncAttributeMaxDynamicSharedMemorySize, SMEM_MMA);
    cudaFuncSetAttribute(gemm_mma<0,1,0>, cudaFuncAttributeMaxDynamicSharedMemorySize, SMEM_MMA);

    const float scale = (float)(1.0 / sqrt((double)DIMN));

    // input conversions
    {
        size_t n4 = (size_t)BATCH * LQ * DIMN / 4;
        split_kernel<<<(unsigned)((n4 + 255) / 256), 256>>>(chunk, ch, cl, n4);
        size_t w4 = (size_t)DIMN * DIMN / 4;
        unsigned wg = (unsigned)((w4 + 255) / 256);
        split_kernel<<<wg, 256>>>(Wq, wqh, wql, w4);
        split_kernel<<<wg, 256>>>(Wk, wkh, wkl, w4);
        split_kernel<<<wg, 256>>>(Wv, wvh, wvl, w4);
        split_kernel<<<wg, 256>>>(Wo, woh, wol, w4);
        size_t ck4 = (size_t)BATCH * KC * DIMN / 4;
        cachek_kernel<<<(unsigned)((ck4 + 255) / 256), 256>>>(cached_k);
        cachev_kernel<<<dim3(KC / 32, DIMN / 32, BATCH), dim3(32, 8)>>>(cached_v);
    }

    // Q projection: [B*L,D] @ Wq^T + bq -> split
    gemm_mma<1,1,0><<<dim3(DIMN / BNT, (BATCH * LQ) / BMT, 1), 256, SMEM_MMA>>>(
        ch, cl, wqh, wql, bq, nullptr, qh, ql,
        DIMN, DIMN, DIMN, DIMN, 0, 0, 0);

    // K projection -> k_full rows [KC, KT) per batch (row stride KTP)
    gemm_mma<1,1,0><<<dim3(DIMN / BNT, LQ / BMT, BATCH), 256, SMEM_MMA>>>(
        ch, cl, wkh, wkl, bk, nullptr, kh + (size_t)KC * DIMN, kl + (size_t)KC * DIMN,
        DIMN, DIMN, DIMN, DIMN,
        (long long)LQ * DIMN, 0, (long long)KTP * DIMN);

    // V^T projection: newV^T = Wv @ chunk^T + bv(row) -> vT cols [KC, KT)
    gemm_mma<1,2,0><<<dim3(LQ / BNT, DIMN / BMT, BATCH), 256, SMEM_MMA>>>(
        wvh, wvl, ch, cl, bv, nullptr, vh + KC, vl + KC,
        DIMN, DIMN, DIMN, KT,
        0, (long long)LQ * DIMN, (long long)DIMN * KT);

    // S = q @ k_full^T (fp32 out; scale folded into softmax; masked tiles skipped)
    gemm_mma<0,0,1><<<dim3(KTP / BNT, LQ / BMT, BATCH), 256, SMEM_MMA>>>(
        qh, ql, kh, kl, nullptr, s, nullptr, nullptr,
        DIMN, DIMN, DIMN, KTP,
        (long long)LQ * DIMN, (long long)KTP * DIMN, (long long)LQ * KTP);

    // masked softmax -> split weights
    softmax_kernel<<<dim3(LQ, BATCH), 256>>>(s, phh, pll, scale);

    // attended = P @ V (NT against V^T), K loop clamped; heavy rows first
    gemm_mma<1,0,2><<<dim3(DIMN / BNT, LQ / BMT, BATCH), 256, SMEM_MMA>>>(
        phh, pll, vh, vl, nullptr, nullptr, ahh, all,
        KT, KT, KT, DIMN,
        (long long)LQ * KT, (long long)DIMN * KT, (long long)LQ * DIMN);

    // output projection: attended @ Wo^T + bo -> fp32 out
    gemm_mma<0,1,0><<<dim3(DIMN / BNT, (BATCH * LQ) / BMT, 1), 256, SMEM_MMA>>>(
        ahh, all, woh, wol, bo, out, nullptr, nullptr,
        DIMN, DIMN, DIMN, DIMN, 0, 0, 0);
}

// round 7
// speedup vs baseline: 5.7152x; 1.5107x over previous
#include <cuda_runtime.h>
#include <cuda_fp16.h>
#include <math.h>
#include <stdint.h>

#define DIMN 2048
#define BATCH 4
#define LQ    4096
#define KC    576
#define KT    4672          // KC + LQ
#define KTP   4864          // padded N for the S GEMM (38*128)

typedef __half h16;

// ---------------------------------------------------------------------------
// Scratch (__device__ globals — zero-initialized; K rows [KT,KTP) stay 0)
// fp16 2-pass scheme: A operands stored hi-only, B operands hi+lo.
// ---------------------------------------------------------------------------
__device__ h16 g_ch [(size_t)BATCH*LQ*DIMN];   // chunk hi (A in Q/K proj)
__device__ h16 g_cl [(size_t)BATCH*LQ*DIMN];   // chunk lo (B in V^T proj)
__device__ h16 g_wqh[(size_t)DIMN*DIMN], g_wql[(size_t)DIMN*DIMN];
__device__ h16 g_wkh[(size_t)DIMN*DIMN], g_wkl[(size_t)DIMN*DIMN];
__device__ h16 g_wvh[(size_t)DIMN*DIMN];                              // A role: hi only
__device__ h16 g_woh[(size_t)DIMN*DIMN], g_wol[(size_t)DIMN*DIMN];
__device__ h16 g_qh [(size_t)BATCH*LQ*DIMN];                          // A role: hi only
__device__ h16 g_kh [(size_t)BATCH*KTP*DIMN], g_kl[(size_t)BATCH*KTP*DIMN];
__device__ h16 g_vh [(size_t)BATCH*DIMN*KT],  g_vl[(size_t)BATCH*DIMN*KT]; // V^T [b][d][kt]
__device__ float g_s [(size_t)BATCH*LQ*KTP];
__device__ h16 g_ph [(size_t)BATCH*LQ*KT];                            // A role: hi only
__device__ h16 g_ah [(size_t)BATCH*LQ*DIMN];                          // A role: hi only

// ---------------------------------------------------------------------------
// helpers
// ---------------------------------------------------------------------------
__device__ __forceinline__ uint32_t s2u(const void* p) {
    uint32_t a;
    asm("{ .reg .u64 t; cvta.to.shared.u64 t, %1; cvt.u32.u64 %0, t; }" : "=r"(a) : "l"(p));
    return a;
}
__device__ __forceinline__ void cpa16(uint32_t d, const void* s) {
    asm volatile("cp.async.cg.shared.global [%0], [%1], 16;" :: "r"(d), "l"(s));
}
#define CP_COMMIT() asm volatile("cp.async.commit_group;" ::: "memory")
#define CP_WAIT1()  asm volatile("cp.async.wait_group 1;" ::: "memory")
#define CP_WAIT0()  asm volatile("cp.async.wait_group 0;" ::: "memory")

#define LDSM4(r, a) \
    asm volatile("ldmatrix.sync.aligned.m8n8.x4.shared.b16 {%0,%1,%2,%3}, [%4];" \
                 : "=r"((r)[0]), "=r"((r)[1]), "=r"((r)[2]), "=r"((r)[3]) : "r"(a))

__device__ __forceinline__ void mma16816(float* d, const uint32_t* a,
                                         uint32_t b0, uint32_t b1) {
    asm volatile(
        "mma.sync.aligned.m16n8k16.row.col.f32.f16.f16.f32 "
        "{%0,%1,%2,%3}, {%4,%5,%6,%7}, {%8,%9}, {%0,%1,%2,%3};"
        : "+f"(d[0]), "+f"(d[1]), "+f"(d[2]), "+f"(d[3])
        : "r"(a[0]), "r"(a[1]), "r"(a[2]), "r"(a[3]), "r"(b0), "r"(b1));
}

// x = hi(fp16) + lo(fp16); residual ~2^-22 |x|
__device__ __forceinline__ void split2h(float x0, float x1, uint32_t& h, uint32_t& l) {
    __half2 hp = __floats2half2_rn(x0, x1);
    float2 hf = __half22float2(hp);
    __half2 lp = __floats2half2_rn(x0 - hf.x, x1 - hf.y);
    h = *reinterpret_cast<uint32_t*>(&hp);
    l = *reinterpret_cast<uint32_t*>(&lp);
}
__device__ __forceinline__ uint32_t round2h(float x0, float x1) {
    __half2 hp = __floats2half2_rn(x0, x1);
    return *reinterpret_cast<uint32_t*>(&hp);
}

// ---------------------------------------------------------------------------
// fp16 2-pass mma.sync GEMM: C tile 128x128, BK=32, 2-stage cp.async pipeline.
// C = Ah·Bh^T + Ah·Bl^T. A[M,K] hi-only, B[N,K] hi+lo, row-major (NT). fp32 acc.
// OUTM: 0 fp32 out, 1 fp16 hi-only out, 2 fp16 hi+lo out.
// BIASM: 0 none, 1 bias[col], 2 bias[row]
// TRI:  0 none, 1 = skip block if col0 >= KC+row0+BMT (S GEMM),
//       2 = clamp K loop to KC+row0+BMT (AV GEMM; heavy rows scheduled first)
// ---------------------------------------------------------------------------
#define BMT 128
#define BNT 128
#define BKT 32
#define APAD 40                          // fp16 row stride (32+8) -> 80B
#define TILE_B (128 * APAD * 2)          // 10240 bytes per tile
#define STAGE_B (3 * TILE_B)             // Ah|Bh|Bl = 30720
#define SMEM_MMA (2 * STAGE_B)           // 61440 bytes

template<int OUTM, int BIASM, int TRI>
__global__ __launch_bounds__(256, 2)
void gemm_mma(const h16* __restrict__ Ah,
              const h16* __restrict__ Bh, const h16* __restrict__ Bl,
              const float* __restrict__ bias,
              float* __restrict__ Cf, h16* __restrict__ Ch, h16* __restrict__ Cl,
              int K, int lda, int ldb, int ldc,
              long long sA, long long sB, long long sC)
{
    // TRI==2: reverse row order so the heaviest (longest-K) CTAs start first
    const int row0 = (TRI == 2 ? (int)(gridDim.y - 1 - blockIdx.y) : (int)blockIdx.y) * BMT;
    const int col0 = blockIdx.x * BNT;
    if (TRI == 1 && col0 >= KC + row0 + BMT) return;   // fully-masked S tile

    extern __shared__ h16 sm[];
    const uint32_t smb = s2u(sm);
    const int tid  = threadIdx.x;
    const int lane = tid & 31, warp = tid >> 5;
    const int wm = warp & 1, wn = warp >> 1;    // warp grid 2 (M) x 4 (N)
    const size_t zA = (size_t)blockIdx.z * sA;
    const size_t zB = (size_t)blockIdx.z * sB;
    const size_t zC = (size_t)blockIdx.z * sC;

    int kchunks = K / BKT;
    if (TRI == 2) {
        int lim = (KC + row0 + BMT) / BKT;      // multiple of 32 by construction
        if (lim < kchunks) kchunks = lim;
    }

    // cp.async mapping: rows (tid>>2) and (tid>>2)+64, 16B chunk (tid&3)*8
    const int lrow = tid >> 2;
    const int lcol = (tid & 3) * 8;
    const uint32_t o1 = (lrow * APAD + lcol) * 2;
    const uint32_t o2 = ((lrow + 64) * APAD + lcol) * 2;

    auto issue = [&](int kc, int st) {
        const size_t ao = zA + (size_t)(row0 + lrow) * lda + (size_t)kc * BKT + lcol;
        const size_t bo = zB + (size_t)(col0 + lrow) * ldb + (size_t)kc * BKT + lcol;
        const uint32_t base = smb + st * STAGE_B;
        cpa16(base + o1,              Ah + ao);
        cpa16(base + o2,              Ah + ao + (size_t)64 * lda);
        cpa16(base + TILE_B + o1,     Bh + bo);
        cpa16(base + TILE_B + o2,     Bh + bo + (size_t)64 * ldb);
        cpa16(base + 2*TILE_B + o1,   Bl + bo);
        cpa16(base + 2*TILE_B + o2,   Bl + bo + (size_t)64 * ldb);
    };

    float acc[4][4][4];
#pragma unroll
    for (int i = 0; i < 4; i++)
#pragma unroll
        for (int j = 0; j < 4; j++)
#pragma unroll
            for (int e = 0; e < 4; e++) acc[i][j][e] = 0.f;

    // ldmatrix per-thread address components
    const int am = wm * 64 + (lane & 15);
    const int ak = (lane >> 4) * 8;
    const int bn = wn * 32 + (lane & 15);

    issue(0, 0); CP_COMMIT();

    for (int kc = 0; kc < kchunks; ++kc) {
        const int st = kc & 1;
        if (kc + 1 < kchunks) { issue(kc + 1, (kc + 1) & 1); CP_COMMIT(); CP_WAIT1(); }
        else                  { CP_WAIT0(); }
        __syncthreads();

        const uint32_t ah_ = smb + st * STAGE_B;
        const uint32_t bh_ = ah_ + TILE_B;
        const uint32_t bl_ = ah_ + 2 * TILE_B;
#pragma unroll
        for (int ks = 0; ks < 2; ks++) {
            uint32_t af[4][4], bh[2][4], bl[2][4];
            // load A(hi) + B(hi), run the hh group
#pragma unroll
            for (int mt = 0; mt < 4; mt++)
                LDSM4(af[mt], ah_ + (((am + mt * 16) * APAD) + ks * 16 + ak) * 2);
#pragma unroll
            for (int pr = 0; pr < 2; pr++)
                LDSM4(bh[pr], bh_ + (((bn + pr * 16) * APAD) + ks * 16 + ak) * 2);
#pragma unroll
            for (int mt = 0; mt < 4; mt++)
#pragma unroll
                for (int nt = 0; nt < 4; nt++)
                    mma16816(acc[mt][nt], af[mt],
                             bh[nt >> 1][nt & 1], bh[nt >> 1][(nt & 1) + 2]);
            // load B(lo) while hh drains, then hl group
#pragma unroll
            for (int pr = 0; pr < 2; pr++)
                LDSM4(bl[pr], bl_ + (((bn + pr * 16) * APAD) + ks * 16 + ak) * 2);
#pragma unroll
            for (int mt = 0; mt < 4; mt++)
#pragma unroll
                for (int nt = 0; nt < 4; nt++)
                    mma16816(acc[mt][nt], af[mt],
                             bl[nt >> 1][nt & 1], bl[nt >> 1][(nt & 1) + 2]);
        }
        __syncthreads();   // stage consumed before it is refilled
    }

    // epilogue
    const int crow = lane >> 2;
    const int ccol = (lane & 3) * 2;
#pragma unroll
    for (int mt = 0; mt < 4; mt++) {
        const size_t r0g = (size_t)row0 + wm * 64 + mt * 16 + crow;
#pragma unroll
        for (int nt = 0; nt < 4; nt++) {
            const int cg = col0 + wn * 32 + nt * 8 + ccol;
            float v0 = acc[mt][nt][0], v1 = acc[mt][nt][1];
            float v2 = acc[mt][nt][2], v3 = acc[mt][nt][3];
            if (BIASM == 1) {
                const float b0 = bias[cg], b1 = bias[cg + 1];
                v0 += b0; v1 += b1; v2 += b0; v3 += b1;
            }
            if (BIASM == 2) {
                const float b0 = bias[r0g], b1 = bias[r0g + 8];
                v0 += b0; v1 += b0; v2 += b1; v3 += b1;
            }
            if (OUTM == 0) {
                *reinterpret_cast<float2*>(&Cf[zC + r0g * ldc + cg])       = make_float2(v0, v1);
                *reinterpret_cast<float2*>(&Cf[zC + (r0g + 8) * ldc + cg]) = make_float2(v2, v3);
            } else if (OUTM == 1) {
                *reinterpret_cast<uint32_t*>(&Ch[zC + r0g * ldc + cg])       = round2h(v0, v1);
                *reinterpret_cast<uint32_t*>(&Ch[zC + (r0g + 8) * ldc + cg]) = round2h(v2, v3);
            } else {
                uint32_t h, l;
                split2h(v0, v1, h, l);
                *reinterpret_cast<uint32_t*>(&Ch[zC + r0g * ldc + cg]) = h;
                *reinterpret_cast<uint32_t*>(&Cl[zC + r0g * ldc + cg]) = l;
                split2h(v2, v3, h, l);
                *reinterpret_cast<uint32_t*>(&Ch[zC + (r0g + 8) * ldc + cg]) = h;
                *reinterpret_cast<uint32_t*>(&Cl[zC + (r0g + 8) * ldc + cg]) = l;
            }
        }
    }
}

// ---------------------------------------------------------------------------
// Elementwise fp32 -> split fp16 (hi+lo) and fp32 -> fp16 (hi only)
// ---------------------------------------------------------------------------
__global__ void split_kernel(const float* __restrict__ src, h16* __restrict__ h,
                             h16* __restrict__ l, size_t n4)
{
    size_t i = (size_t)blockIdx.x * blockDim.x + threadIdx.x;
    if (i >= n4) return;
    float4 v = reinterpret_cast<const float4*>(src)[i];
    uint32_t h0, h1, l0, l1;
    split2h(v.x, v.y, h0, l0);
    split2h(v.z, v.w, h1, l1);
    reinterpret_cast<uint2*>(h)[i] = make_uint2(h0, h1);
    reinterpret_cast<uint2*>(l)[i] = make_uint2(l0, l1);
}

__global__ void round_kernel(const float* __restrict__ src, h16* __restrict__ h, size_t n4)
{
    size_t i = (size_t)blockIdx.x * blockDim.x + threadIdx.x;
    if (i >= n4) return;
    float4 v = reinterpret_cast<const float4*>(src)[i];
    reinterpret_cast<uint2*>(h)[i] = make_uint2(round2h(v.x, v.y), round2h(v.z, v.w));
}

__global__ void cachek_kernel(const float* __restrict__ ck)
{
    const size_t per = (size_t)KC * DIMN / 4;
    size_t i = (size_t)blockIdx.x * blockDim.x + threadIdx.x;
    if (i >= BATCH * per) return;
    size_t b = i / per, r = i - b * per;
    float4 v = reinterpret_cast<const float4*>(ck)[i];
    uint32_t h0, h1, l0, l1;
    split2h(v.x, v.y, h0, l0);
    split2h(v.z, v.w, h1, l1);
    size_t dst = b * ((size_t)KTP * DIMN / 4) + r;
    reinterpret_cast<uint2*>(g_kh)[dst] = make_uint2(h0, h1);
    reinterpret_cast<uint2*>(g_kl)[dst] = make_uint2(l0, l1);
}

// cached_v [B,KC,D] -> transposed split into g_vh/g_vl [B,D,KT] cols [0,KC)
__global__ void cachev_kernel(const float* __restrict__ cv)
{
    __shared__ float t[32][33];
    const int b = blockIdx.z;
    const int r0 = blockIdx.x * 32;   // kc
    const int c0 = blockIdx.y * 32;   // d
    const int tx = threadIdx.x, ty0 = threadIdx.y;
#pragma unroll
    for (int s = 0; s < 4; s++) {
        int ty = ty0 + s * 8;
        t[ty][tx] = cv[((size_t)b * KC + r0 + ty) * DIMN + c0 + tx];
    }
    __syncthreads();
#pragma unroll
    for (int s = 0; s < 4; s++) {
        int ty = ty0 + s * 8;
        float x = t[tx][ty];
        __half h = __float2half_rn(x);
        __half lo = __float2half_rn(x - __half2float(h));
        size_t o = ((size_t)b * DIMN + c0 + ty) * KT + r0 + tx;
        g_vh[o] = h;
        g_vl[o] = lo;
    }
}

// ---------------------------------------------------------------------------
// Masked softmax: row q sees [0, KC+q+1); emits fp16 weights (0 beyond).
// ---------------------------------------------------------------------------
__global__ void softmax_kernel(const float* __restrict__ S, h16* __restrict__ Wh,
                               float scale)
{
    __shared__ float sbuf[KT];
    __shared__ float red[256];
    const int q = blockIdx.x, b = blockIdx.y;
    const float* row = S + ((size_t)b * LQ + q) * KTP;
    h16* wh = Wh + ((size_t)b * LQ + q) * KT;
    const int valid = KC + q + 1;
    const int tid = threadIdx.x;

    float m = -1e30f;
    for (int c = tid; c < valid; c += 256) m = fmaxf(m, row[c] * scale);
    red[tid] = m; __syncthreads();
    for (int s = 128; s > 0; s >>= 1) { if (tid < s) red[tid] = fmaxf(red[tid], red[tid + s]); __syncthreads(); }
    m = red[0]; __syncthreads();

    float sum = 0.f;
    for (int c = tid; c < valid; c += 256) {
        float e = __expf(row[c] * scale - m);
        sbuf[c] = e;
        sum += e;
    }
    red[tid] = sum; __syncthreads();
    for (int s = 128; s > 0; s >>= 1) { if (tid < s) red[tid] += red[tid + s]; __syncthreads(); }
    const float inv = 1.f / red[0];
    __syncthreads();

    for (int c = tid; c < KT; c += 256)
        wh[c] = __float2half_rn((c < valid) ? sbuf[c] * inv : 0.f);
}

// ---------------------------------------------------------------------------
// kernel_launch
// ---------------------------------------------------------------------------
extern "C" void kernel_launch(void* const* d_in, const int* in_sizes, int n_in,
                              void* d_out, int out_size)
{
    const float* chunk    = (const float*)d_in[0];
    const float* cached_k = (const float*)d_in[1];
    const float* cached_v = (const float*)d_in[2];
    int wi = 3;
    while (wi < n_in && in_sizes[wi] != DIMN * DIMN) wi++;
    const float* Wq = (const float*)d_in[wi + 0];
    const float* bq = (const float*)d_in[wi + 1];
    const float* Wk = (const float*)d_in[wi + 2];
    const float* bk = (const float*)d_in[wi + 3];
    const float* Wv = (const float*)d_in[wi + 4];
    const float* bv = (const float*)d_in[wi + 5];
    const float* Wo = (const float*)d_in[wi + 6];
    const float* bo = (const float*)d_in[wi + 7];
    float* out = (float*)d_out;

    h16 *ch, *cl, *wqh, *wql, *wkh, *wkl, *wvh, *woh, *wol;
    h16 *qh, *kh, *kl, *vh, *vl, *phh, *ahh;
    float* s;
    cudaGetSymbolAddress((void**)&ch, g_ch);   cudaGetSymbolAddress((void**)&cl, g_cl);
    cudaGetSymbolAddress((void**)&wqh, g_wqh); cudaGetSymbolAddress((void**)&wql, g_wql);
    cudaGetSymbolAddress((void**)&wkh, g_wkh); cudaGetSymbolAddress((void**)&wkl, g_wkl);
    cudaGetSymbolAddress((void**)&wvh, g_wvh);
    cudaGetSymbolAddress((void**)&woh, g_woh); cudaGetSymbolAddress((void**)&wol, g_wol);
    cudaGetSymbolAddress((void**)&qh, g_qh);
    cudaGetSymbolAddress((void**)&kh, g_kh);   cudaGetSymbolAddress((void**)&kl, g_kl);
    cudaGetSymbolAddress((void**)&vh, g_vh);   cudaGetSymbolAddress((void**)&vl, g_vl);
    cudaGetSymbolAddress((void**)&s, g_s);
    cudaGetSymbolAddress((void**)&phh, g_ph);
    cudaGetSymbolAddress((void**)&ahh, g_ah);

    cudaFuncSetAttribute(gemm_mma<1,1,0>, cudaFuncAttributeMaxDynamicSharedMemorySize, SMEM_MMA);
    cudaFuncSetAttribute(gemm_mma<2,1,0>, cudaFuncAttributeMaxDynamicSharedMemorySize, SMEM_MMA);
    cudaFuncSetAttribute(gemm_mma<2,2,0>, cudaFuncAttributeMaxDynamicSharedMemorySize, SMEM_MMA);
    cudaFuncSetAttribute(gemm_mma<0,0,1>, cudaFuncAttributeMaxDynamicSharedMemorySize, SMEM_MMA);
    cudaFuncSetAttribute(gemm_mma<1,0,2>, cudaFuncAttributeMaxDynamicSharedMemorySize, SMEM_MMA);
    cudaFuncSetAttribute(gemm_mma<0,1,0>, cudaFuncAttributeMaxDynamicSharedMemorySize, SMEM_MMA);

    const float scale = (float)(1.0 / sqrt((double)DIMN));

    // input conversions
    {
        size_t n4 = (size_t)BATCH * LQ * DIMN / 4;
        split_kernel<<<(unsigned)((n4 + 255) / 256), 256>>>(chunk, ch, cl, n4);
        size_t w4 = (size_t)DIMN * DIMN / 4;
        unsigned wg = (unsigned)((w4 + 255) / 256);
        split_kernel<<<wg, 256>>>(Wq, wqh, wql, w4);
        split_kernel<<<wg, 256>>>(Wk, wkh, wkl, w4);
        round_kernel<<<wg, 256>>>(Wv, wvh, w4);
        split_kernel<<<wg, 256>>>(Wo, woh, wol, w4);
        size_t ck4 = (size_t)BATCH * KC * DIMN / 4;
        cachek_kernel<<<(unsigned)((ck4 + 255) / 256), 256>>>(cached_k);
        cachev_kernel<<<dim3(KC / 32, DIMN / 32, BATCH), dim3(32, 8)>>>(cached_v);
    }

    // Q projection: chunk(hi) @ (Wq hi+lo)^T + bq -> Q hi-only
    gemm_mma<1,1,0><<<dim3(DIMN / BNT, (BATCH * LQ) / BMT, 1), 256, SMEM_MMA>>>(
        ch, wqh, wql, bq, nullptr, qh, nullptr,
        DIMN, DIMN, DIMN, DIMN, 0, 0, 0);

    // K projection -> k_full rows [KC, KT), hi+lo (K is B operand of S GEMM)
    gemm_mma<2,1,0><<<dim3(DIMN / BNT, LQ / BMT, BATCH), 256, SMEM_MMA>>>(
        ch, wkh, wkl, bk, nullptr, kh + (size_t)KC * DIMN, kl + (size_t)KC * DIMN,
        DIMN, DIMN, DIMN, DIMN,
        (long long)LQ * DIMN, 0, (long long)KTP * DIMN);

    // V^T projection: Wv(hi) @ (chunk hi+lo)^T + bv(row) -> vT cols [KC,KT), hi+lo
    gemm_mma<2,2,0><<<dim3(LQ / BNT, DIMN / BMT, BATCH), 256, SMEM_MMA>>>(
        wvh, ch, cl, bv, nullptr, vh + KC, vl + KC,
        DIMN, DIMN, DIMN, KT,
        0, (long long)LQ * DIMN, (long long)DIMN * KT);

    // S = Q(hi) @ (K hi+lo)^T (fp32 out; scale folded into softmax; masked tiles skipped)
    gemm_mma<0,0,1><<<dim3(KTP / BNT, LQ / BMT, BATCH), 256, SMEM_MMA>>>(
        qh, kh, kl, nullptr, s, nullptr, nullptr,
        DIMN, DIMN, DIMN, KTP,
        (long long)LQ * DIMN, (long long)KTP * DIMN, (long long)LQ * KTP);

    // masked softmax -> fp16 weights
    softmax_kernel<<<dim3(LQ, BATCH), 256>>>(s, phh, scale);

    // attended = P(hi) @ (V^T hi+lo), K loop clamped; heavy rows first; hi-only out
    gemm_mma<1,0,2><<<dim3(DIMN / BNT, LQ / BMT, BATCH), 256, SMEM_MMA>>>(
        phh, vh, vl, nullptr, nullptr, ahh, nullptr,
        KT, KT, KT, DIMN,
        (long long)LQ * KT, (long long)DIMN * KT, (long long)LQ * DIMN);

    // output projection: attended(hi) @ (Wo hi+lo)^T + bo -> fp32 out
    gemm_mma<0,1,0><<<dim3(DIMN / BNT, (BATCH * LQ) / BMT, 1), 256, SMEM_MMA>>>(
        ahh, woh, wol, bo, out, nullptr, nullptr,
        DIMN, DIMN, DIMN, DIMN, 0, 0, 0);
}